// round 5
// baseline (speedup 1.0000x reference)
#include <cuda_runtime.h>
#include <math.h>

#define NT 256
typedef unsigned long long ull;

// Paired (f32x2) constant weights — all source layouts are contiguous pairs.
__constant__ ull cW2b2[1024];  // W2b [64][32]
__constant__ ull cb2b2[16];
__constant__ ull cW2c2[512];   // W2c [32][32]
__constant__ ull cb2c2[16];
__constant__ ull cW45_2[64];   // W2a rows 64,65 (edge-feature rank-2 weights)

// Shared layout (float offsets)
#define OFF_NT    0        // nodeT [32 feat][32 node] stride 33 = 1056
#define OFF_H     1056     // [32][65] = 2080
#define OFF_MI    3136     // [32][36] = 1152
#define OFF_EDGE  4288     // [992][2] = 1984
#define OFF_BASE  6272     // [32][66] = 2112
#define OFF_PROJ  8384     // [32][66] = 2112
#define OFF_A     10496    // staging W2a[0:64]+b2a (4160) / readout t1
#define SMEM_FLOATS 14656  // 58,624 B

__device__ __forceinline__ float gelu_f(float x) {
    return 0.5f * x * (1.0f + erff(x * 0.7071067811865476f));
}
__device__ __forceinline__ float sigm_f(float x) {
    return 1.0f / (1.0f + __expf(-x));
}
__device__ __forceinline__ ull pack2(float lo, float hi) {
    ull r; asm("mov.b64 %0, {%1, %2};" : "=l"(r) : "f"(lo), "f"(hi)); return r;
}
__device__ __forceinline__ ull dup2(float x) { return pack2(x, x); }
__device__ __forceinline__ void unpack2(ull v, float& lo, float& hi) {
    asm("mov.b64 {%0, %1}, %2;" : "=f"(lo), "=f"(hi) : "l"(v));
}
__device__ __forceinline__ ull fma2(ull a, ull b, ull c) {
    ull d; asm("fma.rn.f32x2 %0, %1, %2, %3;" : "=l"(d) : "l"(a), "l"(b), "l"(c));
    return d;
}
__device__ __forceinline__ ull add2(ull a, ull b) {
    ull d; asm("add.rn.f32x2 %0, %1, %2;" : "=l"(d) : "l"(a), "l"(b));
    return d;
}
__device__ __forceinline__ ull shfl64(ull v, int src) {
    unsigned lo = (unsigned)v, hi = (unsigned)(v >> 32);
    lo = __shfl_sync(0xffffffffu, lo, src);
    hi = __shfl_sync(0xffffffffu, hi, src);
    return ((ull)hi << 32) | lo;
}
__device__ __forceinline__ ull shflxor64(ull v, int m) {
    unsigned lo = (unsigned)v, hi = (unsigned)(v >> 32);
    lo = __shfl_xor_sync(0xffffffffu, lo, m);
    hi = __shfl_xor_sync(0xffffffffu, hi, m);
    return ((ull)hi << 32) | lo;
}

#define FMA8(acc, a, w0, w1) do { \
    acc[0] += (a) * (w0).x; acc[1] += (a) * (w0).y; \
    acc[2] += (a) * (w0).z; acc[3] += (a) * (w0).w; \
    acc[4] += (a) * (w1).x; acc[5] += (a) * (w1).y; \
    acc[6] += (a) * (w1).z; acc[7] += (a) * (w1).w; } while (0)

struct GnnParams {
    const float *node0, *edge, *h0, *mean, *vari;
    const int   *iterp;
    const float *W1a, *b1a, *W2a, *b2a;
    const float *Wih, *Whh, *bih, *bhh, *W3b, *b3b;
    const float *W4a, *b4a, *W4b, *b4b, *W4c, *b4c, *W5a, *b5a, *W5b, *b5b;
    float *out;
};

__global__ __launch_bounds__(NT, 2)
void gnn_kernel(GnnParams p) {
    extern __shared__ float sm[];
    const int tid  = threadIdx.x;
    const int b    = blockIdx.x;
    const int warp = tid >> 5, lane = tid & 31;

    float* sNT   = sm + OFF_NT;    // node^T [feat][node], stride 33
    float* sH    = sm + OFF_H;     // stride 65
    float* sMi   = sm + OFF_MI;    // stride 36
    float* sEdge = sm + OFF_EDGE;
    float* sBase = sm + OFF_BASE;  // stride 66
    float* sProj = sm + OFF_PROJ;  // stride 66
    float* bufA  = sm + OFF_A;

    // ---- init copies ----
    for (int i = tid; i < 992*2; i += NT) sEdge[i] = p.edge[b*1984 + i];
    for (int i = tid; i < 32*64; i += NT) {
        int n = i >> 6, k = i & 63;
        sH[n*65 + k] = p.h0[b*2048 + i];
    }
    for (int i = tid; i < 1024; i += NT) bufA[i] = p.node0[b*1024 + i];
    if (tid < 32) {
        sMi[tid*36 + 32] = p.mean[b*32 + tid];
        sMi[tid*36 + 33] = 1.0f / p.vari[b*32 + tid];
    }
    __syncthreads();

    // ---- node = node0 @ W1a + b1a (write transposed into sNT) ----
    {
        const int n = tid >> 3, f0 = (tid & 7) << 2;
        float a0 = p.b1a[f0], a1 = p.b1a[f0+1], a2 = p.b1a[f0+2], a3 = p.b1a[f0+3];
        const float* r = bufA + n*32;
        #pragma unroll 8
        for (int k = 0; k < 32; ++k) {
            float a = r[k];
            float4 w = *(const float4*)(p.W1a + k*32 + f0);
            a0 += a*w.x; a1 += a*w.y; a2 += a*w.z; a3 += a*w.w;
        }
        sNT[(f0+0)*33 + n] = a0; sNT[(f0+1)*33 + n] = a1;
        sNT[(f0+2)*33 + n] = a2; sNT[(f0+3)*33 + n] = a3;
    }
    __syncthreads();

    const int iters = p.iterp ? *p.iterp : 3;

    for (int it = 0; it < iters; ++it) {
        // ---- stage W2a rows 0..63 + b2a into bufA ----
        for (int i = tid; i < 4096; i += NT) bufA[i] = p.W2a[i];
        for (int i = tid + 4096; i < 4160; i += NT) bufA[i] = p.b2a[i - 4096];
        __syncthreads();

        // ---- base = node@W2a[0:32]+b2a ; proj = node@W2a[32:64] ----
        {
            const int n = tid >> 3, c0 = (tid & 7) << 3;
            ull bacc[4], pacc[4];
            {
                ulonglong2 b0 = *(const ulonglong2*)(bufA + 4096 + c0);
                ulonglong2 b1 = *(const ulonglong2*)(bufA + 4096 + c0 + 4);
                bacc[0]=b0.x; bacc[1]=b0.y; bacc[2]=b1.x; bacc[3]=b1.y;
            }
            const ull z = dup2(0.0f);
            #pragma unroll
            for (int o = 0; o < 4; ++o) pacc[o] = z;
            #pragma unroll 4
            for (int k = 0; k < 32; ++k) {
                ull aa = dup2(sNT[k*33 + n]);
                ulonglong2 wb0 = *(const ulonglong2*)(bufA + k*64 + c0);
                ulonglong2 wb1 = *(const ulonglong2*)(bufA + k*64 + c0 + 4);
                ulonglong2 wp0 = *(const ulonglong2*)(bufA + (32+k)*64 + c0);
                ulonglong2 wp1 = *(const ulonglong2*)(bufA + (32+k)*64 + c0 + 4);
                bacc[0] = fma2(aa, wb0.x, bacc[0]); bacc[1] = fma2(aa, wb0.y, bacc[1]);
                bacc[2] = fma2(aa, wb1.x, bacc[2]); bacc[3] = fma2(aa, wb1.y, bacc[3]);
                pacc[0] = fma2(aa, wp0.x, pacc[0]); pacc[1] = fma2(aa, wp0.y, pacc[1]);
                pacc[2] = fma2(aa, wp1.x, pacc[2]); pacc[3] = fma2(aa, wp1.y, pacc[3]);
            }
            #pragma unroll
            for (int o = 0; o < 4; ++o) {
                *(ull*)(sBase + n*66 + c0 + 2*o) = bacc[o];
                *(ull*)(sProj + n*66 + c0 + 2*o) = pacc[o];
            }
        }
        __syncthreads();

        // ---- edge phase: warp = node i, lane = edge q; no smem round-trips ----
        for (int pass = 0; pass < 4; ++pass) {
            const int i = pass * 8 + warp;
            const int q = (lane < 31) ? lane : 30;
            const int j = q + (q >= i);
            const ull bsu = *(const ull*)(sBase + i*66 + 2*lane);
            const ull ev  = *(const ull*)(sEdge + (i*31 + q)*2);
            float e0f, e1f; unpack2(ev, e0f, e1f);
            const ull e0d = dup2(e0f), e1d = dup2(e1f);
            const float* prj = sProj + j*66;

            ull acc[16];
            #pragma unroll
            for (int cp = 0; cp < 16; ++cp) acc[cp] = cb2b2[cp];

            #pragma unroll 4
            for (int t = 0; t < 32; ++t) {
                ull bst = shfl64(bsu, t);
                ull pr2 = *(const ull*)(prj + 2*t);
                ull u = add2(bst, pr2);
                u = fma2(e0d, cW45_2[t], u);
                u = fma2(e1d, cW45_2[32 + t], u);
                float g0, g1; unpack2(u, g0, g1);
                ull a0 = dup2(gelu_f(g0)), a1 = dup2(gelu_f(g1));
                #pragma unroll
                for (int cp = 0; cp < 16; ++cp) {
                    acc[cp] = fma2(a0, cW2b2[(2*t)*16 + cp], acc[cp]);
                    acc[cp] = fma2(a1, cW2b2[(2*t+1)*16 + cp], acc[cp]);
                }
            }

            // layer 3 from registers
            ull macc[16];
            #pragma unroll
            for (int cp = 0; cp < 16; ++cp) macc[cp] = cb2c2[cp];
            #pragma unroll 4
            for (int cqp = 0; cqp < 16; ++cqp) {
                float v0, v1; unpack2(acc[cqp], v0, v1);
                ull a0 = dup2(gelu_f(v0)), a1 = dup2(gelu_f(v1));
                #pragma unroll
                for (int cp = 0; cp < 16; ++cp) {
                    macc[cp] = fma2(a0, cW2c2[(2*cqp)*16 + cp], macc[cp]);
                    macc[cp] = fma2(a1, cW2c2[(2*cqp+1)*16 + cp], macc[cp]);
                }
            }

            // gelu + mask dummy lane + warp segment-sum
            #pragma unroll
            for (int cp = 0; cp < 16; ++cp) {
                float v0, v1; unpack2(macc[cp], v0, v1);
                macc[cp] = (lane < 31) ? pack2(gelu_f(v0), gelu_f(v1)) : 0ULL;
            }
            #pragma unroll
            for (int off = 16; off; off >>= 1) {
                #pragma unroll
                for (int cp = 0; cp < 16; ++cp)
                    macc[cp] = add2(macc[cp], shflxor64(macc[cp], off));
            }
            if (lane < 16) *(ull*)(sMi + i*36 + 2*lane) = macc[lane];
        }
        __syncthreads();

        // ---- GRU cell (GELU new gate), packed col-pairs ----
        {
            const int n  = tid >> 3;
            const int c0 = (tid & 7) << 3;
            ull ar[4], az[4], an_[4], hn_[4];
            #pragma unroll
            for (int o = 0; o < 4; ++o) {
                ull bi_r = *(const ull*)(p.bih + c0 + 2*o);
                ull bh_r = *(const ull*)(p.bhh + c0 + 2*o);
                ull bi_z = *(const ull*)(p.bih + 64 + c0 + 2*o);
                ull bh_z = *(const ull*)(p.bhh + 64 + c0 + 2*o);
                ar[o]  = add2(bi_r, bh_r);
                az[o]  = add2(bi_z, bh_z);
                an_[o] = *(const ull*)(p.bih + 128 + c0 + 2*o);
                hn_[o] = *(const ull*)(p.bhh + 128 + c0 + 2*o);
            }
            const float* mi = sMi + n*36;
            #pragma unroll 2
            for (int k = 0; k < 34; ++k) {
                ull aa = dup2(mi[k]);
                const float* w = p.Wih + k*192;
                ulonglong2 r01 = *(const ulonglong2*)(w + c0);
                ulonglong2 r23 = *(const ulonglong2*)(w + c0 + 4);
                ulonglong2 z01 = *(const ulonglong2*)(w + 64 + c0);
                ulonglong2 z23 = *(const ulonglong2*)(w + 64 + c0 + 4);
                ulonglong2 n01 = *(const ulonglong2*)(w + 128 + c0);
                ulonglong2 n23 = *(const ulonglong2*)(w + 128 + c0 + 4);
                ar[0]=fma2(aa,r01.x,ar[0]); ar[1]=fma2(aa,r01.y,ar[1]);
                ar[2]=fma2(aa,r23.x,ar[2]); ar[3]=fma2(aa,r23.y,ar[3]);
                az[0]=fma2(aa,z01.x,az[0]); az[1]=fma2(aa,z01.y,az[1]);
                az[2]=fma2(aa,z23.x,az[2]); az[3]=fma2(aa,z23.y,az[3]);
                an_[0]=fma2(aa,n01.x,an_[0]); an_[1]=fma2(aa,n01.y,an_[1]);
                an_[2]=fma2(aa,n23.x,an_[2]); an_[3]=fma2(aa,n23.y,an_[3]);
            }
            const float* hv = sH + n*65;
            #pragma unroll 2
            for (int k = 0; k < 64; ++k) {
                ull aa = dup2(hv[k]);
                const float* w = p.Whh + k*192;
                ulonglong2 r01 = *(const ulonglong2*)(w + c0);
                ulonglong2 r23 = *(const ulonglong2*)(w + c0 + 4);
                ulonglong2 z01 = *(const ulonglong2*)(w + 64 + c0);
                ulonglong2 z23 = *(const ulonglong2*)(w + 64 + c0 + 4);
                ulonglong2 n01 = *(const ulonglong2*)(w + 128 + c0);
                ulonglong2 n23 = *(const ulonglong2*)(w + 128 + c0 + 4);
                ar[0]=fma2(aa,r01.x,ar[0]); ar[1]=fma2(aa,r01.y,ar[1]);
                ar[2]=fma2(aa,r23.x,ar[2]); ar[3]=fma2(aa,r23.y,ar[3]);
                az[0]=fma2(aa,z01.x,az[0]); az[1]=fma2(aa,z01.y,az[1]);
                az[2]=fma2(aa,z23.x,az[2]); az[3]=fma2(aa,z23.y,az[3]);
                hn_[0]=fma2(aa,n01.x,hn_[0]); hn_[1]=fma2(aa,n01.y,hn_[1]);
                hn_[2]=fma2(aa,n23.x,hn_[2]); hn_[3]=fma2(aa,n23.y,hn_[3]);
            }
            float hnew[8];
            #pragma unroll
            for (int o = 0; o < 4; ++o) {
                float r0, r1, z0, z1, in0, in1, hn0, hn1;
                unpack2(ar[o], r0, r1);
                unpack2(az[o], z0, z1);
                unpack2(an_[o], in0, in1);
                unpack2(hn_[o], hn0, hn1);
                float rr0 = sigm_f(r0), rr1 = sigm_f(r1);
                float zz0 = sigm_f(z0), zz1 = sigm_f(z1);
                float g0 = gelu_f(in0 + rr0 * hn0);
                float g1 = gelu_f(in1 + rr1 * hn1);
                hnew[2*o]   = (1.0f - zz0) * g0 + zz0 * hv[c0 + 2*o];
                hnew[2*o+1] = (1.0f - zz1) * g1 + zz1 * hv[c0 + 2*o + 1];
            }
            __syncthreads();
            #pragma unroll
            for (int o = 0; o < 8; ++o) sH[n*65 + c0 + o] = hnew[o];
        }
        __syncthreads();

        // ---- node = h @ W3b + b3b  (packed, write transposed into sNT) ----
        {
            const int n = tid >> 3, f0 = (tid & 7) << 2;
            ull a01 = *(const ull*)(p.b3b + f0);
            ull a23 = *(const ull*)(p.b3b + f0 + 2);
            const float* hv = sH + n*65;
            #pragma unroll 4
            for (int k = 0; k < 64; ++k) {
                ull aa = dup2(hv[k]);
                ulonglong2 w2 = *(const ulonglong2*)(p.W3b + k*32 + f0);
                a01 = fma2(aa, w2.x, a01);
                a23 = fma2(aa, w2.y, a23);
            }
            float v0, v1, v2, v3;
            unpack2(a01, v0, v1); unpack2(a23, v2, v3);
            sNT[(f0+0)*33 + n] = v0; sNT[(f0+1)*33 + n] = v1;
            sNT[(f0+2)*33 + n] = v2; sNT[(f0+3)*33 + n] = v3;
        }
        __syncthreads();
    }

    // ---- readout (scratch: bufA=t1, sBase=t2, sProj=t3, sBase=t4) ----
    {   // t1 = node @ W4a + b4a : [32][68]
        const int n = tid >> 3, f0 = (tid & 7) << 3;
        ull acc[4];
        acc[0] = *(const ull*)(p.b4a + f0);
        acc[1] = *(const ull*)(p.b4a + f0 + 2);
        acc[2] = *(const ull*)(p.b4a + f0 + 4);
        acc[3] = *(const ull*)(p.b4a + f0 + 6);
        #pragma unroll 4
        for (int k = 0; k < 32; ++k) {
            ull aa = dup2(sNT[k*33 + n]);
            ulonglong2 w0 = *(const ulonglong2*)(p.W4a + k*64 + f0);
            ulonglong2 w1 = *(const ulonglong2*)(p.W4a + k*64 + f0 + 4);
            acc[0] = fma2(aa, w0.x, acc[0]); acc[1] = fma2(aa, w0.y, acc[1]);
            acc[2] = fma2(aa, w1.x, acc[2]); acc[3] = fma2(aa, w1.y, acc[3]);
        }
        #pragma unroll
        for (int o = 0; o < 4; ++o) *(ull*)(bufA + n*68 + f0 + 2*o) = acc[o];
    }
    __syncthreads();
    {   // t2 = t1 @ W4b + b4b : [32][36] into sBase
        const int n = tid >> 3, f0 = (tid & 7) << 2;
        ull a01 = *(const ull*)(p.b4b + f0);
        ull a23 = *(const ull*)(p.b4b + f0 + 2);
        const float* r = bufA + n*68;
        #pragma unroll 4
        for (int k = 0; k < 64; ++k) {
            ull aa = dup2(r[k]);
            ulonglong2 w2 = *(const ulonglong2*)(p.W4b + k*32 + f0);
            a01 = fma2(aa, w2.x, a01);
            a23 = fma2(aa, w2.y, a23);
        }
        *(ull*)(sBase + n*36 + f0)     = a01;
        *(ull*)(sBase + n*36 + f0 + 2) = a23;
    }
    __syncthreads();
    {   // t3 = t2 @ W4c + b4c : [32][36] into sProj
        const int n = tid >> 3, f0 = (tid & 7) << 2;
        ull a01 = *(const ull*)(p.b4c + f0);
        ull a23 = *(const ull*)(p.b4c + f0 + 2);
        const float* r = sBase + n*36;
        #pragma unroll 4
        for (int k = 0; k < 32; ++k) {
            ull aa = dup2(r[k]);
            ulonglong2 w2 = *(const ulonglong2*)(p.W4c + k*32 + f0);
            a01 = fma2(aa, w2.x, a01);
            a23 = fma2(aa, w2.y, a23);
        }
        *(ull*)(sProj + n*36 + f0)     = a01;
        *(ull*)(sProj + n*36 + f0 + 2) = a23;
    }
    __syncthreads();
    {   // t4 = t3 @ W5a + b5a : [32][18] into sBase
        const int n = tid >> 3, f0 = (tid & 7) << 1;
        float a0 = p.b5a[f0], a1 = p.b5a[f0 + 1];
        const float* r = sProj + n*36;
        #pragma unroll 8
        for (int k = 0; k < 32; ++k) {
            float a = r[k];
            a0 += a * p.W5a[k*16 + f0];
            a1 += a * p.W5a[k*16 + f0 + 1];
        }
        sBase[n*18 + f0]     = a0;
        sBase[n*18 + f0 + 1] = a1;
    }
    __syncthreads();
    if (tid < 64) {
        const int n = tid >> 1, col = tid & 1;
        float acc = p.b5b[col];
        const float* r = sBase + n*18;
        #pragma unroll
        for (int k = 0; k < 16; ++k) acc += r[k] * p.W5b[k*2 + col];
        if (col == 0) p.out[b*32 + n] = acc;
        else          p.out[32768 + b*32 + n] = 1.0f / acc;
    }
}

extern "C" void kernel_launch(void* const* d_in, const int* in_sizes, int n_in,
                              void* d_out, int out_size) {
    const int has_iter = (n_in >= 32) ? 1 : 0;
    const int base = has_iter ? 8 : 7;

    GnnParams p;
    p.node0 = (const float*)d_in[0];
    p.edge  = (const float*)d_in[1];
    p.h0    = (const float*)d_in[2];
    p.mean  = (const float*)d_in[3];
    p.vari  = (const float*)d_in[4];
    p.iterp = has_iter ? (const int*)d_in[7] : nullptr;
    p.W1a = (const float*)d_in[base+0];  p.b1a = (const float*)d_in[base+1];
    p.W2a = (const float*)d_in[base+2];  p.b2a = (const float*)d_in[base+3];
    const void* W2b = d_in[base+4];      const void* b2b = d_in[base+5];
    const void* W2c = d_in[base+6];      const void* b2c = d_in[base+7];
    p.Wih = (const float*)d_in[base+8];  p.Whh = (const float*)d_in[base+9];
    p.bih = (const float*)d_in[base+10]; p.bhh = (const float*)d_in[base+11];
    p.W3b = (const float*)d_in[base+12]; p.b3b = (const float*)d_in[base+13];
    p.W4a = (const float*)d_in[base+14]; p.b4a = (const float*)d_in[base+15];
    p.W4b = (const float*)d_in[base+16]; p.b4b = (const float*)d_in[base+17];
    p.W4c = (const float*)d_in[base+18]; p.b4c = (const float*)d_in[base+19];
    p.W5a = (const float*)d_in[base+20]; p.b5a = (const float*)d_in[base+21];
    p.W5b = (const float*)d_in[base+22]; p.b5b = (const float*)d_in[base+23];
    p.out = (float*)d_out;

    // Stage small weights into __constant__ (D2D async copies, graph-capturable).
    cudaMemcpyToSymbolAsync(cW2b2, W2b, 64*32*sizeof(float), 0,
                            cudaMemcpyDeviceToDevice);
    cudaMemcpyToSymbolAsync(cb2b2, b2b, 32*sizeof(float), 0,
                            cudaMemcpyDeviceToDevice);
    cudaMemcpyToSymbolAsync(cW2c2, W2c, 32*32*sizeof(float), 0,
                            cudaMemcpyDeviceToDevice);
    cudaMemcpyToSymbolAsync(cb2c2, b2c, 32*sizeof(float), 0,
                            cudaMemcpyDeviceToDevice);
    cudaMemcpyToSymbolAsync(cW45_2, (const float*)d_in[base+2] + 64*64,
                            128*sizeof(float), 0, cudaMemcpyDeviceToDevice);

    cudaFuncSetAttribute(gnn_kernel,
                         cudaFuncAttributeMaxDynamicSharedMemorySize,
                         SMEM_FLOATS * (int)sizeof(float));
    gnn_kernel<<<1024, NT, SMEM_FLOATS * sizeof(float)>>>(p);
}

// round 6
// speedup vs baseline: 1.1412x; 1.1412x over previous
#include <cuda_runtime.h>
#include <math.h>

#define NT 256
typedef unsigned long long ull;

// Shared layout (float offsets)
#define OFF_NT    0        // nodeT [32 feat][32 node] stride 33 = 1056
#define OFF_H     1056     // [32][65] = 2080
#define OFF_MI    3136     // [32][36] = 1152
#define OFF_EDGE  4288     // [992][2] = 1984
#define OFF_BASE  6272     // [32][66] = 2112
#define OFF_PROJ  8384     // [32][66] = 2112
#define OFF_A     10496    // staging W2a[0:64]+b2a (4160) / readout t1 (2176)
#define OFF_W2B2  14656    // W2b as ull pairs: 2048 floats
#define OFF_W2C2  16704    // W2c as ull pairs: 1024 floats
#define OFF_W45S  17728    // W2a rows 64,65: 128 floats
#define OFF_B2B   17856    // 32
#define OFF_B2C   17888    // 32
#define SMEM_FLOATS 17920  // 71,680 B -> 2 CTAs/SM

__device__ __forceinline__ float gelu_f(float x) {
    return 0.5f * x * (1.0f + erff(x * 0.7071067811865476f));
}
__device__ __forceinline__ float sigm_f(float x) {
    return 1.0f / (1.0f + __expf(-x));
}
__device__ __forceinline__ ull pack2(float lo, float hi) {
    ull r; asm("mov.b64 %0, {%1, %2};" : "=l"(r) : "f"(lo), "f"(hi)); return r;
}
__device__ __forceinline__ ull dup2(float x) { return pack2(x, x); }
__device__ __forceinline__ void unpack2(ull v, float& lo, float& hi) {
    asm("mov.b64 {%0, %1}, %2;" : "=f"(lo), "=f"(hi) : "l"(v));
}
__device__ __forceinline__ ull fma2(ull a, ull b, ull c) {
    ull d; asm("fma.rn.f32x2 %0, %1, %2, %3;" : "=l"(d) : "l"(a), "l"(b), "l"(c));
    return d;
}
__device__ __forceinline__ ull add2(ull a, ull b) {
    ull d; asm("add.rn.f32x2 %0, %1, %2;" : "=l"(d) : "l"(a), "l"(b));
    return d;
}
__device__ __forceinline__ ull shflxor64(ull v, int m) {
    unsigned lo = (unsigned)v, hi = (unsigned)(v >> 32);
    lo = __shfl_xor_sync(0xffffffffu, lo, m);
    hi = __shfl_xor_sync(0xffffffffu, hi, m);
    return ((ull)hi << 32) | lo;
}

struct GnnParams {
    const float *node0, *edge, *h0, *mean, *vari;
    const int   *iterp;
    const float *W1a, *b1a, *W2a, *b2a, *W2b, *b2b, *W2c, *b2c;
    const float *Wih, *Whh, *bih, *bhh, *W3b, *b3b;
    const float *W4a, *b4a, *W4b, *b4b, *W4c, *b4c, *W5a, *b5a, *W5b, *b5b;
    float *out;
};

__global__ __launch_bounds__(NT, 2)
void gnn_kernel(GnnParams p) {
    extern __shared__ float sm[];
    const int tid  = threadIdx.x;
    const int b    = blockIdx.x;
    const int warp = tid >> 5, lane = tid & 31;

    float* sNT   = sm + OFF_NT;    // node^T [feat][node], stride 33
    float* sH    = sm + OFF_H;     // stride 65
    float* sMi   = sm + OFF_MI;    // stride 36
    float* sEdge = sm + OFF_EDGE;
    float* sBase = sm + OFF_BASE;  // stride 66
    float* sProj = sm + OFF_PROJ;  // stride 66
    float* bufA  = sm + OFF_A;
    const ull* wB   = (const ull*)(sm + OFF_W2B2);
    const ull* wC   = (const ull*)(sm + OFF_W2C2);
    const ull* w45u = (const ull*)(sm + OFF_W45S);
    const ull* bB   = (const ull*)(sm + OFF_B2B);
    const ull* bC   = (const ull*)(sm + OFF_B2C);

    // ---- init copies (once) ----
    for (int i = tid; i < 992*2; i += NT) sEdge[i] = p.edge[b*1984 + i];
    for (int i = tid; i < 32*64; i += NT) {
        int n = i >> 6, k = i & 63;
        sH[n*65 + k] = p.h0[b*2048 + i];
    }
    for (int i = tid; i < 2048;  i += NT) sm[OFF_W2B2 + i] = p.W2b[i];
    for (int i = tid; i < 1024;  i += NT) sm[OFF_W2C2 + i] = p.W2c[i];
    for (int i = tid; i < 128;   i += NT) sm[OFF_W45S + i] = p.W2a[64*64 + i];
    for (int i = tid; i < 32;    i += NT) {
        sm[OFF_B2B + i] = p.b2b[i];
        sm[OFF_B2C + i] = p.b2c[i];
    }
    if (tid < 32) {
        sMi[tid*36 + 32] = p.mean[b*32 + tid];
        sMi[tid*36 + 33] = 1.0f / p.vari[b*32 + tid];
    }
    // node0 into sBase temporarily for the input projection
    for (int i = tid; i < 1024; i += NT) sBase[i] = p.node0[b*1024 + i];
    // stage W2a rows 0..63 + b2a into bufA (persists across iterations)
    for (int i = tid; i < 4096; i += NT) bufA[i] = p.W2a[i];
    for (int i = tid + 4096; i < 4160; i += NT) bufA[i] = p.b2a[i - 4096];
    __syncthreads();

    // ---- node = node0 @ W1a + b1a (write transposed into sNT) ----
    {
        const int n = tid >> 3, f0 = (tid & 7) << 2;
        float a0 = p.b1a[f0], a1 = p.b1a[f0+1], a2 = p.b1a[f0+2], a3 = p.b1a[f0+3];
        const float* r = sBase + n*32;
        #pragma unroll 8
        for (int k = 0; k < 32; ++k) {
            float a = r[k];
            float4 w = *(const float4*)(p.W1a + k*32 + f0);
            a0 += a*w.x; a1 += a*w.y; a2 += a*w.z; a3 += a*w.w;
        }
        sNT[(f0+0)*33 + n] = a0; sNT[(f0+1)*33 + n] = a1;
        sNT[(f0+2)*33 + n] = a2; sNT[(f0+3)*33 + n] = a3;
    }
    __syncthreads();

    const int iters = p.iterp ? *p.iterp : 3;

    for (int it = 0; it < iters; ++it) {
        // ---- base = node@W2a[0:32]+b2a ; proj = node@W2a[32:64] ----
        {
            const int n = tid >> 3, c0 = (tid & 7) << 3;
            ull bacc[4], pacc[4];
            {
                ulonglong2 b0 = *(const ulonglong2*)(bufA + 4096 + c0);
                ulonglong2 b1 = *(const ulonglong2*)(bufA + 4096 + c0 + 4);
                bacc[0]=b0.x; bacc[1]=b0.y; bacc[2]=b1.x; bacc[3]=b1.y;
            }
            const ull z = dup2(0.0f);
            #pragma unroll
            for (int o = 0; o < 4; ++o) pacc[o] = z;
            #pragma unroll 4
            for (int k = 0; k < 32; ++k) {
                ull aa = dup2(sNT[k*33 + n]);
                ulonglong2 wb0 = *(const ulonglong2*)(bufA + k*64 + c0);
                ulonglong2 wb1 = *(const ulonglong2*)(bufA + k*64 + c0 + 4);
                ulonglong2 wp0 = *(const ulonglong2*)(bufA + (32+k)*64 + c0);
                ulonglong2 wp1 = *(const ulonglong2*)(bufA + (32+k)*64 + c0 + 4);
                bacc[0] = fma2(aa, wb0.x, bacc[0]); bacc[1] = fma2(aa, wb0.y, bacc[1]);
                bacc[2] = fma2(aa, wb1.x, bacc[2]); bacc[3] = fma2(aa, wb1.y, bacc[3]);
                pacc[0] = fma2(aa, wp0.x, pacc[0]); pacc[1] = fma2(aa, wp0.y, pacc[1]);
                pacc[2] = fma2(aa, wp1.x, pacc[2]); pacc[3] = fma2(aa, wp1.y, pacc[3]);
            }
            #pragma unroll
            for (int o = 0; o < 4; ++o) {
                *(ull*)(sBase + n*66 + c0 + 2*o) = bacc[o];
                *(ull*)(sProj + n*66 + c0 + 2*o) = pacc[o];
            }
        }
        __syncthreads();

        // ---- edge phase: warp = node i, lane = edge q; weights via smem bcast ----
        for (int pass = 0; pass < 4; ++pass) {
            const int i = pass * 8 + warp;
            const int q = (lane < 31) ? lane : 30;
            const int j = q + (q >= i);
            const ull ev = *(const ull*)(sEdge + (i*31 + q)*2);
            float e0f, e1f; unpack2(ev, e0f, e1f);
            const ull e0d = dup2(e0f), e1d = dup2(e1f);
            const float* prj = sProj + j*66;
            const float* bas = sBase + i*66;

            ull acc[16];
            #pragma unroll
            for (int cp = 0; cp < 16; ++cp) acc[cp] = bB[cp];

            #pragma unroll 4
            for (int t = 0; t < 32; ++t) {
                ull bst = *(const ull*)(bas + 2*t);   // warp-uniform: broadcast
                ull pr2 = *(const ull*)(prj + 2*t);
                ull u = add2(bst, pr2);
                u = fma2(e0d, w45u[t], u);
                u = fma2(e1d, w45u[32 + t], u);
                float g0, g1; unpack2(u, g0, g1);
                ull a0 = dup2(gelu_f(g0)), a1 = dup2(gelu_f(g1));
                #pragma unroll
                for (int cp2 = 0; cp2 < 8; ++cp2) {
                    ulonglong2 w0 = *(const ulonglong2*)(wB + (2*t)*16 + 2*cp2);
                    ulonglong2 w1 = *(const ulonglong2*)(wB + (2*t+1)*16 + 2*cp2);
                    acc[2*cp2]   = fma2(a0, w0.x, acc[2*cp2]);
                    acc[2*cp2+1] = fma2(a0, w0.y, acc[2*cp2+1]);
                    acc[2*cp2]   = fma2(a1, w1.x, acc[2*cp2]);
                    acc[2*cp2+1] = fma2(a1, w1.y, acc[2*cp2+1]);
                }
            }

            // layer 3 from registers
            ull macc[16];
            #pragma unroll
            for (int cp = 0; cp < 16; ++cp) macc[cp] = bC[cp];
            #pragma unroll 4
            for (int cqp = 0; cqp < 16; ++cqp) {
                float v0, v1; unpack2(acc[cqp], v0, v1);
                ull a0 = dup2(gelu_f(v0)), a1 = dup2(gelu_f(v1));
                #pragma unroll
                for (int cp2 = 0; cp2 < 8; ++cp2) {
                    ulonglong2 w0 = *(const ulonglong2*)(wC + (2*cqp)*16 + 2*cp2);
                    ulonglong2 w1 = *(const ulonglong2*)(wC + (2*cqp+1)*16 + 2*cp2);
                    macc[2*cp2]   = fma2(a0, w0.x, macc[2*cp2]);
                    macc[2*cp2+1] = fma2(a0, w0.y, macc[2*cp2+1]);
                    macc[2*cp2]   = fma2(a1, w1.x, macc[2*cp2]);
                    macc[2*cp2+1] = fma2(a1, w1.y, macc[2*cp2+1]);
                }
            }

            // gelu + mask dummy lane + warp segment-sum
            #pragma unroll
            for (int cp = 0; cp < 16; ++cp) {
                float v0, v1; unpack2(macc[cp], v0, v1);
                macc[cp] = (lane < 31) ? pack2(gelu_f(v0), gelu_f(v1)) : 0ULL;
            }
            #pragma unroll
            for (int off = 16; off; off >>= 1) {
                #pragma unroll
                for (int cp = 0; cp < 16; ++cp)
                    macc[cp] = add2(macc[cp], shflxor64(macc[cp], off));
            }
            if (lane < 16) *(ull*)(sMi + i*36 + 2*lane) = macc[lane];
        }
        __syncthreads();

        // ---- GRU cell (GELU new gate), packed col-pairs ----
        {
            const int n  = tid >> 3;
            const int c0 = (tid & 7) << 3;
            ull ar[4], az[4], an_[4], hn_[4];
            #pragma unroll
            for (int o = 0; o < 4; ++o) {
                ull bi_r = *(const ull*)(p.bih + c0 + 2*o);
                ull bh_r = *(const ull*)(p.bhh + c0 + 2*o);
                ull bi_z = *(const ull*)(p.bih + 64 + c0 + 2*o);
                ull bh_z = *(const ull*)(p.bhh + 64 + c0 + 2*o);
                ar[o]  = add2(bi_r, bh_r);
                az[o]  = add2(bi_z, bh_z);
                an_[o] = *(const ull*)(p.bih + 128 + c0 + 2*o);
                hn_[o] = *(const ull*)(p.bhh + 128 + c0 + 2*o);
            }
            const float* mi = sMi + n*36;
            #pragma unroll 2
            for (int k = 0; k < 34; ++k) {
                ull aa = dup2(mi[k]);
                const float* w = p.Wih + k*192;
                ulonglong2 r01 = *(const ulonglong2*)(w + c0);
                ulonglong2 r23 = *(const ulonglong2*)(w + c0 + 4);
                ulonglong2 z01 = *(const ulonglong2*)(w + 64 + c0);
                ulonglong2 z23 = *(const ulonglong2*)(w + 64 + c0 + 4);
                ulonglong2 n01 = *(const ulonglong2*)(w + 128 + c0);
                ulonglong2 n23 = *(const ulonglong2*)(w + 128 + c0 + 4);
                ar[0]=fma2(aa,r01.x,ar[0]); ar[1]=fma2(aa,r01.y,ar[1]);
                ar[2]=fma2(aa,r23.x,ar[2]); ar[3]=fma2(aa,r23.y,ar[3]);
                az[0]=fma2(aa,z01.x,az[0]); az[1]=fma2(aa,z01.y,az[1]);
                az[2]=fma2(aa,z23.x,az[2]); az[3]=fma2(aa,z23.y,az[3]);
                an_[0]=fma2(aa,n01.x,an_[0]); an_[1]=fma2(aa,n01.y,an_[1]);
                an_[2]=fma2(aa,n23.x,an_[2]); an_[3]=fma2(aa,n23.y,an_[3]);
            }
            const float* hv = sH + n*65;
            #pragma unroll 2
            for (int k = 0; k < 64; ++k) {
                ull aa = dup2(hv[k]);
                const float* w = p.Whh + k*192;
                ulonglong2 r01 = *(const ulonglong2*)(w + c0);
                ulonglong2 r23 = *(const ulonglong2*)(w + c0 + 4);
                ulonglong2 z01 = *(const ulonglong2*)(w + 64 + c0);
                ulonglong2 z23 = *(const ulonglong2*)(w + 64 + c0 + 4);
                ulonglong2 n01 = *(const ulonglong2*)(w + 128 + c0);
                ulonglong2 n23 = *(const ulonglong2*)(w + 128 + c0 + 4);
                ar[0]=fma2(aa,r01.x,ar[0]); ar[1]=fma2(aa,r01.y,ar[1]);
                ar[2]=fma2(aa,r23.x,ar[2]); ar[3]=fma2(aa,r23.y,ar[3]);
                az[0]=fma2(aa,z01.x,az[0]); az[1]=fma2(aa,z01.y,az[1]);
                az[2]=fma2(aa,z23.x,az[2]); az[3]=fma2(aa,z23.y,az[3]);
                hn_[0]=fma2(aa,n01.x,hn_[0]); hn_[1]=fma2(aa,n01.y,hn_[1]);
                hn_[2]=fma2(aa,n23.x,hn_[2]); hn_[3]=fma2(aa,n23.y,hn_[3]);
            }
            float hnew[8];
            #pragma unroll
            for (int o = 0; o < 4; ++o) {
                float r0, r1, z0, z1, in0, in1, hn0, hn1;
                unpack2(ar[o], r0, r1);
                unpack2(az[o], z0, z1);
                unpack2(an_[o], in0, in1);
                unpack2(hn_[o], hn0, hn1);
                float rr0 = sigm_f(r0), rr1 = sigm_f(r1);
                float zz0 = sigm_f(z0), zz1 = sigm_f(z1);
                float g0 = gelu_f(in0 + rr0 * hn0);
                float g1 = gelu_f(in1 + rr1 * hn1);
                hnew[2*o]   = (1.0f - zz0) * g0 + zz0 * hv[c0 + 2*o];
                hnew[2*o+1] = (1.0f - zz1) * g1 + zz1 * hv[c0 + 2*o + 1];
            }
            __syncthreads();
            #pragma unroll
            for (int o = 0; o < 8; ++o) sH[n*65 + c0 + o] = hnew[o];
        }
        __syncthreads();

        // ---- node = h @ W3b + b3b  (packed, write transposed into sNT) ----
        {
            const int n = tid >> 3, f0 = (tid & 7) << 2;
            ull a01 = *(const ull*)(p.b3b + f0);
            ull a23 = *(const ull*)(p.b3b + f0 + 2);
            const float* hv = sH + n*65;
            #pragma unroll 4
            for (int k = 0; k < 64; ++k) {
                ull aa = dup2(hv[k]);
                ulonglong2 w2 = *(const ulonglong2*)(p.W3b + k*32 + f0);
                a01 = fma2(aa, w2.x, a01);
                a23 = fma2(aa, w2.y, a23);
            }
            float v0, v1, v2, v3;
            unpack2(a01, v0, v1); unpack2(a23, v2, v3);
            sNT[(f0+0)*33 + n] = v0; sNT[(f0+1)*33 + n] = v1;
            sNT[(f0+2)*33 + n] = v2; sNT[(f0+3)*33 + n] = v3;
        }
        __syncthreads();
    }

    // ---- readout (scratch: bufA=t1, sBase=t2, sProj=t3, sBase=t4) ----
    {   // t1 = node @ W4a + b4a : [32][68]
        const int n = tid >> 3, f0 = (tid & 7) << 3;
        ull acc[4];
        acc[0] = *(const ull*)(p.b4a + f0);
        acc[1] = *(const ull*)(p.b4a + f0 + 2);
        acc[2] = *(const ull*)(p.b4a + f0 + 4);
        acc[3] = *(const ull*)(p.b4a + f0 + 6);
        #pragma unroll 4
        for (int k = 0; k < 32; ++k) {
            ull aa = dup2(sNT[k*33 + n]);
            ulonglong2 w0 = *(const ulonglong2*)(p.W4a + k*64 + f0);
            ulonglong2 w1 = *(const ulonglong2*)(p.W4a + k*64 + f0 + 4);
            acc[0] = fma2(aa, w0.x, acc[0]); acc[1] = fma2(aa, w0.y, acc[1]);
            acc[2] = fma2(aa, w1.x, acc[2]); acc[3] = fma2(aa, w1.y, acc[3]);
        }
        #pragma unroll
        for (int o = 0; o < 4; ++o) *(ull*)(bufA + n*68 + f0 + 2*o) = acc[o];
    }
    __syncthreads();
    {   // t2 = t1 @ W4b + b4b : [32][36] into sBase
        const int n = tid >> 3, f0 = (tid & 7) << 2;
        ull a01 = *(const ull*)(p.b4b + f0);
        ull a23 = *(const ull*)(p.b4b + f0 + 2);
        const float* r = bufA + n*68;
        #pragma unroll 4
        for (int k = 0; k < 64; ++k) {
            ull aa = dup2(r[k]);
            ulonglong2 w2 = *(const ulonglong2*)(p.W4b + k*32 + f0);
            a01 = fma2(aa, w2.x, a01);
            a23 = fma2(aa, w2.y, a23);
        }
        *(ull*)(sBase + n*36 + f0)     = a01;
        *(ull*)(sBase + n*36 + f0 + 2) = a23;
    }
    __syncthreads();
    {   // t3 = t2 @ W4c + b4c : [32][36] into sProj
        const int n = tid >> 3, f0 = (tid & 7) << 2;
        ull a01 = *(const ull*)(p.b4c + f0);
        ull a23 = *(const ull*)(p.b4c + f0 + 2);
        const float* r = sBase + n*36;
        #pragma unroll 4
        for (int k = 0; k < 32; ++k) {
            ull aa = dup2(r[k]);
            ulonglong2 w2 = *(const ulonglong2*)(p.W4c + k*32 + f0);
            a01 = fma2(aa, w2.x, a01);
            a23 = fma2(aa, w2.y, a23);
        }
        *(ull*)(sProj + n*36 + f0)     = a01;
        *(ull*)(sProj + n*36 + f0 + 2) = a23;
    }
    __syncthreads();
    {   // t4 = t3 @ W5a + b5a : [32][18] into sBase
        const int n = tid >> 3, f0 = (tid & 7) << 1;
        float a0 = p.b5a[f0], a1 = p.b5a[f0 + 1];
        const float* r = sProj + n*36;
        #pragma unroll 8
        for (int k = 0; k < 32; ++k) {
            float a = r[k];
            a0 += a * p.W5a[k*16 + f0];
            a1 += a * p.W5a[k*16 + f0 + 1];
        }
        sBase[n*18 + f0]     = a0;
        sBase[n*18 + f0 + 1] = a1;
    }
    __syncthreads();
    if (tid < 64) {
        const int n = tid >> 1, col = tid & 1;
        float acc = p.b5b[col];
        const float* r = sBase + n*18;
        #pragma unroll
        for (int k = 0; k < 16; ++k) acc += r[k] * p.W5b[k*2 + col];
        if (col == 0) p.out[b*32 + n] = acc;
        else          p.out[32768 + b*32 + n] = 1.0f / acc;
    }
}

extern "C" void kernel_launch(void* const* d_in, const int* in_sizes, int n_in,
                              void* d_out, int out_size) {
    const int has_iter = (n_in >= 32) ? 1 : 0;
    const int base = has_iter ? 8 : 7;

    GnnParams p;
    p.node0 = (const float*)d_in[0];
    p.edge  = (const float*)d_in[1];
    p.h0    = (const float*)d_in[2];
    p.mean  = (const float*)d_in[3];
    p.vari  = (const float*)d_in[4];
    p.iterp = has_iter ? (const int*)d_in[7] : nullptr;
    p.W1a = (const float*)d_in[base+0];  p.b1a = (const float*)d_in[base+1];
    p.W2a = (const float*)d_in[base+2];  p.b2a = (const float*)d_in[base+3];
    p.W2b = (const float*)d_in[base+4];  p.b2b = (const float*)d_in[base+5];
    p.W2c = (const float*)d_in[base+6];  p.b2c = (const float*)d_in[base+7];
    p.Wih = (const float*)d_in[base+8];  p.Whh = (const float*)d_in[base+9];
    p.bih = (const float*)d_in[base+10]; p.bhh = (const float*)d_in[base+11];
    p.W3b = (const float*)d_in[base+12]; p.b3b = (const float*)d_in[base+13];
    p.W4a = (const float*)d_in[base+14]; p.b4a = (const float*)d_in[base+15];
    p.W4b = (const float*)d_in[base+16]; p.b4b = (const float*)d_in[base+17];
    p.W4c = (const float*)d_in[base+18]; p.b4c = (const float*)d_in[base+19];
    p.W5a = (const float*)d_in[base+20]; p.b5a = (const float*)d_in[base+21];
    p.W5b = (const float*)d_in[base+22]; p.b5b = (const float*)d_in[base+23];
    p.out = (float*)d_out;

    cudaFuncSetAttribute(gnn_kernel,
                         cudaFuncAttributeMaxDynamicSharedMemorySize,
                         SMEM_FLOATS * (int)sizeof(float));
    gnn_kernel<<<1024, NT, SMEM_FLOATS * sizeof(float)>>>(p);
}

// round 7
// speedup vs baseline: 1.4436x; 1.2649x over previous
#include <cuda_runtime.h>
#include <math.h>

#define NT 256
typedef unsigned long long ull;

// Shared layout (float offsets)
#define OFF_NT    0        // nodeT [32 feat][32 node] stride 33 = 1056
#define OFF_H     1056     // [32][65] = 2080
#define OFF_MI    3136     // [32][36] = 1152
#define OFF_EDGE  4288     // [992][2] = 1984
#define OFF_BASE  6272     // [32][66] = 2112
#define OFF_PROJ  8384     // [32][66] = 2112
#define OFF_A     10496    // staging W2a[0:64]+b2a (4160) / readout t1 (2176)
#define OFF_W2B2  14656    // W2b: 2048 floats
#define OFF_W2C2  16704    // W2c: 1024 floats
#define OFF_W45S  17728    // W2a rows 64,65: 128 floats
#define OFF_B2B   17856    // 32
#define OFF_B2C   17888    // 32
#define SMEM_FLOATS 17920  // 71,680 B -> 2 CTAs/SM

__device__ __forceinline__ float gelu_f(float x) {
    return 0.5f * x * (1.0f + erff(x * 0.7071067811865476f));
}
__device__ __forceinline__ float sigm_f(float x) {
    return 1.0f / (1.0f + __expf(-x));
}
__device__ __forceinline__ ull pack2(float lo, float hi) {
    ull r; asm("mov.b64 %0, {%1, %2};" : "=l"(r) : "f"(lo), "f"(hi)); return r;
}
__device__ __forceinline__ ull dup2(float x) { return pack2(x, x); }
__device__ __forceinline__ void unpack2(ull v, float& lo, float& hi) {
    asm("mov.b64 {%0, %1}, %2;" : "=f"(lo), "=f"(hi) : "l"(v));
}
__device__ __forceinline__ ull fma2(ull a, ull b, ull c) {
    ull d; asm("fma.rn.f32x2 %0, %1, %2, %3;" : "=l"(d) : "l"(a), "l"(b), "l"(c));
    return d;
}
__device__ __forceinline__ ull add2(ull a, ull b) {
    ull d; asm("add.rn.f32x2 %0, %1, %2;" : "=l"(d) : "l"(a), "l"(b));
    return d;
}
__device__ __forceinline__ ull shflxor64(ull v, int m) {
    unsigned lo = (unsigned)v, hi = (unsigned)(v >> 32);
    lo = __shfl_xor_sync(0xffffffffu, lo, m);
    hi = __shfl_xor_sync(0xffffffffu, hi, m);
    return ((ull)hi << 32) | lo;
}

struct GnnParams {
    const float *node0, *edge, *h0, *mean, *vari;
    const int   *iterp;
    const float *W1a, *b1a, *W2a, *b2a, *W2b, *b2b, *W2c, *b2c;
    const float *Wih, *Whh, *bih, *bhh, *W3b, *b3b;
    const float *W4a, *b4a, *W4b, *b4b, *W4c, *b4c, *W5a, *b5a, *W5b, *b5b;
    float *out;
};

__global__ __launch_bounds__(NT, 2)
void gnn_kernel(GnnParams p) {
    extern __shared__ float sm[];
    const int tid  = threadIdx.x;
    const int b    = blockIdx.x;
    const int warp = tid >> 5, lane = tid & 31;

    float* sNT   = sm + OFF_NT;
    float* sH    = sm + OFF_H;     // stride 65
    float* sMi   = sm + OFF_MI;    // stride 36
    float* sEdge = sm + OFF_EDGE;
    float* sBase = sm + OFF_BASE;  // stride 66
    float* sProj = sm + OFF_PROJ;  // stride 66
    float* bufA  = sm + OFF_A;
    const ull* wB   = (const ull*)(sm + OFF_W2B2);
    const ull* wC   = (const ull*)(sm + OFF_W2C2);
    const ull* w45u = (const ull*)(sm + OFF_W45S);
    const ull* bB   = (const ull*)(sm + OFF_B2B);
    const ull* bC   = (const ull*)(sm + OFF_B2C);

    // ---- init copies (once) ----
    for (int i = tid; i < 992*2; i += NT) sEdge[i] = p.edge[b*1984 + i];
    for (int i = tid; i < 32*64; i += NT) {
        int n = i >> 6, k = i & 63;
        sH[n*65 + k] = p.h0[b*2048 + i];
    }
    for (int i = tid; i < 2048;  i += NT) sm[OFF_W2B2 + i] = p.W2b[i];
    for (int i = tid; i < 1024;  i += NT) sm[OFF_W2C2 + i] = p.W2c[i];
    for (int i = tid; i < 128;   i += NT) sm[OFF_W45S + i] = p.W2a[64*64 + i];
    for (int i = tid; i < 32;    i += NT) {
        sm[OFF_B2B + i] = p.b2b[i];
        sm[OFF_B2C + i] = p.b2c[i];
    }
    if (tid < 32) {
        sMi[tid*36 + 32] = p.mean[b*32 + tid];
        sMi[tid*36 + 33] = 1.0f / p.vari[b*32 + tid];
    }
    for (int i = tid; i < 1024; i += NT) sBase[i] = p.node0[b*1024 + i];
    for (int i = tid; i < 4096; i += NT) bufA[i] = p.W2a[i];
    for (int i = tid + 4096; i < 4160; i += NT) bufA[i] = p.b2a[i - 4096];
    __syncthreads();

    // ---- node = node0 @ W1a + b1a (write transposed into sNT) ----
    {
        const int n = tid >> 3, f0 = (tid & 7) << 2;
        float a0 = p.b1a[f0], a1 = p.b1a[f0+1], a2 = p.b1a[f0+2], a3 = p.b1a[f0+3];
        const float* r = sBase + n*32;
        #pragma unroll 8
        for (int k = 0; k < 32; ++k) {
            float a = r[k];
            float4 w = *(const float4*)(p.W1a + k*32 + f0);
            a0 += a*w.x; a1 += a*w.y; a2 += a*w.z; a3 += a*w.w;
        }
        sNT[(f0+0)*33 + n] = a0; sNT[(f0+1)*33 + n] = a1;
        sNT[(f0+2)*33 + n] = a2; sNT[(f0+3)*33 + n] = a3;
    }
    __syncthreads();

    const int iters = p.iterp ? *p.iterp : 3;

    for (int it = 0; it < iters; ++it) {
        // ---- base = node@W2a[0:32]+b2a ; proj = node@W2a[32:64] ----
        {
            const int n = tid >> 3, c0 = (tid & 7) << 3;
            ull bacc[4], pacc[4];
            {
                ulonglong2 b0 = *(const ulonglong2*)(bufA + 4096 + c0);
                ulonglong2 b1 = *(const ulonglong2*)(bufA + 4096 + c0 + 4);
                bacc[0]=b0.x; bacc[1]=b0.y; bacc[2]=b1.x; bacc[3]=b1.y;
            }
            const ull z = dup2(0.0f);
            #pragma unroll
            for (int o = 0; o < 4; ++o) pacc[o] = z;
            #pragma unroll 4
            for (int k = 0; k < 32; ++k) {
                ull aa = dup2(sNT[k*33 + n]);
                ulonglong2 wb0 = *(const ulonglong2*)(bufA + k*64 + c0);
                ulonglong2 wb1 = *(const ulonglong2*)(bufA + k*64 + c0 + 4);
                ulonglong2 wp0 = *(const ulonglong2*)(bufA + (32+k)*64 + c0);
                ulonglong2 wp1 = *(const ulonglong2*)(bufA + (32+k)*64 + c0 + 4);
                bacc[0] = fma2(aa, wb0.x, bacc[0]); bacc[1] = fma2(aa, wb0.y, bacc[1]);
                bacc[2] = fma2(aa, wb1.x, bacc[2]); bacc[3] = fma2(aa, wb1.y, bacc[3]);
                pacc[0] = fma2(aa, wp0.x, pacc[0]); pacc[1] = fma2(aa, wp0.y, pacc[1]);
                pacc[2] = fma2(aa, wp1.x, pacc[2]); pacc[3] = fma2(aa, wp1.y, pacc[3]);
            }
            #pragma unroll
            for (int o = 0; o < 4; ++o) {
                *(ull*)(sBase + n*66 + c0 + 2*o) = bacc[o];
                *(ull*)(sProj + n*66 + c0 + 2*o) = pacc[o];
            }
        }
        __syncthreads();

        // ---- edge phase: warp = node i, lane = edge q; register-resident ----
        for (int pass = 0; pass < 4; ++pass) {
            const int i = pass * 8 + warp;
            const int q = (lane < 31) ? lane : 30;
            const int j = q + (q >= i);
            const ull ev = *(const ull*)(sEdge + (i*31 + q)*2);
            float e0f, e1f; unpack2(ev, e0f, e1f);
            const ull e0d = dup2(e0f), e1d = dup2(e1f);
            const float* prj = sProj + j*66;
            const float* bas = sBase + i*66;

            ull acc[16];
            #pragma unroll
            for (int cp = 0; cp < 16; ++cp) acc[cp] = bB[cp];

            #pragma unroll 4
            for (int t = 0; t < 32; ++t) {
                ull bst = *(const ull*)(bas + 2*t);   // warp-uniform: broadcast
                ull pr2 = *(const ull*)(prj + 2*t);
                ull u = add2(bst, pr2);
                u = fma2(e0d, w45u[t], u);
                u = fma2(e1d, w45u[32 + t], u);
                float g0, g1; unpack2(u, g0, g1);
                ull a0 = dup2(gelu_f(g0)), a1 = dup2(gelu_f(g1));
                #pragma unroll
                for (int cp2 = 0; cp2 < 8; ++cp2) {
                    ulonglong2 w0 = *(const ulonglong2*)(wB + (2*t)*16 + 2*cp2);
                    ulonglong2 w1 = *(const ulonglong2*)(wB + (2*t+1)*16 + 2*cp2);
                    acc[2*cp2]   = fma2(a0, w0.x, acc[2*cp2]);
                    acc[2*cp2+1] = fma2(a0, w0.y, acc[2*cp2+1]);
                    acc[2*cp2]   = fma2(a1, w1.x, acc[2*cp2]);
                    acc[2*cp2+1] = fma2(a1, w1.y, acc[2*cp2+1]);
                }
            }

            // layer 3 from registers
            ull macc[16];
            #pragma unroll
            for (int cp = 0; cp < 16; ++cp) macc[cp] = bC[cp];
            #pragma unroll 4
            for (int cqp = 0; cqp < 16; ++cqp) {
                float v0, v1; unpack2(acc[cqp], v0, v1);
                ull a0 = dup2(gelu_f(v0)), a1 = dup2(gelu_f(v1));
                #pragma unroll
                for (int cp2 = 0; cp2 < 8; ++cp2) {
                    ulonglong2 w0 = *(const ulonglong2*)(wC + (2*cqp)*16 + 2*cp2);
                    ulonglong2 w1 = *(const ulonglong2*)(wC + (2*cqp+1)*16 + 2*cp2);
                    macc[2*cp2]   = fma2(a0, w0.x, macc[2*cp2]);
                    macc[2*cp2+1] = fma2(a0, w0.y, macc[2*cp2+1]);
                    macc[2*cp2]   = fma2(a1, w1.x, macc[2*cp2]);
                    macc[2*cp2+1] = fma2(a1, w1.y, macc[2*cp2+1]);
                }
            }

            // gelu + mask dummy lane
            #pragma unroll
            for (int cp = 0; cp < 16; ++cp) {
                float v0, v1; unpack2(macc[cp], v0, v1);
                macc[cp] = (lane < 31) ? pack2(gelu_f(v0), gelu_f(v1)) : 0ULL;
            }
            // Butterfly transpose-reduce: lane ends with the full edge-sum of
            // element bitrev4(lane&15) in macc[0] (STATIC index — no local mem).
            #pragma unroll
            for (int s = 0; s < 4; ++s) {
                const int off = 1 << s;
                const int h = 8 >> s;
                const bool keep_low = ((lane >> s) & 1) == 0;
                #pragma unroll
                for (int r = 0; r < 8; ++r) {
                    if (r < h) {
                        ull send = keep_low ? macc[r + h] : macc[r];
                        ull recv = shflxor64(send, off);
                        ull mine = keep_low ? macc[r] : macc[r + h];
                        macc[r] = add2(mine, recv);
                    }
                }
            }
            macc[0] = add2(macc[0], shflxor64(macc[0], 16));
            if (lane < 16) {
                const int e = ((lane & 1) << 3) | (((lane >> 1) & 1) << 2) |
                              (((lane >> 2) & 1) << 1) | ((lane >> 3) & 1);
                *(ull*)(sMi + i*36 + 2*e) = macc[0];
            }
        }
        __syncthreads();

        // ---- GRU cell (GELU new gate), packed col-pairs ----
        {
            const int n  = tid >> 3;
            const int c0 = (tid & 7) << 3;
            ull ar[4], az[4], an_[4], hn_[4];
            #pragma unroll
            for (int o = 0; o < 4; ++o) {
                ull bi_r = *(const ull*)(p.bih + c0 + 2*o);
                ull bh_r = *(const ull*)(p.bhh + c0 + 2*o);
                ull bi_z = *(const ull*)(p.bih + 64 + c0 + 2*o);
                ull bh_z = *(const ull*)(p.bhh + 64 + c0 + 2*o);
                ar[o]  = add2(bi_r, bh_r);
                az[o]  = add2(bi_z, bh_z);
                an_[o] = *(const ull*)(p.bih + 128 + c0 + 2*o);
                hn_[o] = *(const ull*)(p.bhh + 128 + c0 + 2*o);
            }
            const float* mi = sMi + n*36;
            #pragma unroll 2
            for (int k = 0; k < 34; ++k) {
                ull aa = dup2(mi[k]);
                const float* w = p.Wih + k*192;
                ulonglong2 r01 = *(const ulonglong2*)(w + c0);
                ulonglong2 r23 = *(const ulonglong2*)(w + c0 + 4);
                ulonglong2 z01 = *(const ulonglong2*)(w + 64 + c0);
                ulonglong2 z23 = *(const ulonglong2*)(w + 64 + c0 + 4);
                ulonglong2 n01 = *(const ulonglong2*)(w + 128 + c0);
                ulonglong2 n23 = *(const ulonglong2*)(w + 128 + c0 + 4);
                ar[0]=fma2(aa,r01.x,ar[0]); ar[1]=fma2(aa,r01.y,ar[1]);
                ar[2]=fma2(aa,r23.x,ar[2]); ar[3]=fma2(aa,r23.y,ar[3]);
                az[0]=fma2(aa,z01.x,az[0]); az[1]=fma2(aa,z01.y,az[1]);
                az[2]=fma2(aa,z23.x,az[2]); az[3]=fma2(aa,z23.y,az[3]);
                an_[0]=fma2(aa,n01.x,an_[0]); an_[1]=fma2(aa,n01.y,an_[1]);
                an_[2]=fma2(aa,n23.x,an_[2]); an_[3]=fma2(aa,n23.y,an_[3]);
            }
            const float* hv = sH + n*65;
            #pragma unroll 2
            for (int k = 0; k < 64; ++k) {
                ull aa = dup2(hv[k]);
                const float* w = p.Whh + k*192;
                ulonglong2 r01 = *(const ulonglong2*)(w + c0);
                ulonglong2 r23 = *(const ulonglong2*)(w + c0 + 4);
                ulonglong2 z01 = *(const ulonglong2*)(w + 64 + c0);
                ulonglong2 z23 = *(const ulonglong2*)(w + 64 + c0 + 4);
                ulonglong2 n01 = *(const ulonglong2*)(w + 128 + c0);
                ulonglong2 n23 = *(const ulonglong2*)(w + 128 + c0 + 4);
                ar[0]=fma2(aa,r01.x,ar[0]); ar[1]=fma2(aa,r01.y,ar[1]);
                ar[2]=fma2(aa,r23.x,ar[2]); ar[3]=fma2(aa,r23.y,ar[3]);
                az[0]=fma2(aa,z01.x,az[0]); az[1]=fma2(aa,z01.y,az[1]);
                az[2]=fma2(aa,z23.x,az[2]); az[3]=fma2(aa,z23.y,az[3]);
                hn_[0]=fma2(aa,n01.x,hn_[0]); hn_[1]=fma2(aa,n01.y,hn_[1]);
                hn_[2]=fma2(aa,n23.x,hn_[2]); hn_[3]=fma2(aa,n23.y,hn_[3]);
            }
            float hnew[8];
            #pragma unroll
            for (int o = 0; o < 4; ++o) {
                float r0, r1, z0, z1, in0, in1, hn0, hn1;
                unpack2(ar[o], r0, r1);
                unpack2(az[o], z0, z1);
                unpack2(an_[o], in0, in1);
                unpack2(hn_[o], hn0, hn1);
                float rr0 = sigm_f(r0), rr1 = sigm_f(r1);
                float zz0 = sigm_f(z0), zz1 = sigm_f(z1);
                float g0 = gelu_f(in0 + rr0 * hn0);
                float g1 = gelu_f(in1 + rr1 * hn1);
                hnew[2*o]   = (1.0f - zz0) * g0 + zz0 * hv[c0 + 2*o];
                hnew[2*o+1] = (1.0f - zz1) * g1 + zz1 * hv[c0 + 2*o + 1];
            }
            __syncthreads();
            #pragma unroll
            for (int o = 0; o < 8; ++o) sH[n*65 + c0 + o] = hnew[o];
        }
        __syncthreads();

        // ---- node = h @ W3b + b3b  (packed, write transposed into sNT) ----
        {
            const int n = tid >> 3, f0 = (tid & 7) << 2;
            ull a01 = *(const ull*)(p.b3b + f0);
            ull a23 = *(const ull*)(p.b3b + f0 + 2);
            const float* hv = sH + n*65;
            #pragma unroll 4
            for (int k = 0; k < 64; ++k) {
                ull aa = dup2(hv[k]);
                ulonglong2 w2 = *(const ulonglong2*)(p.W3b + k*32 + f0);
                a01 = fma2(aa, w2.x, a01);
                a23 = fma2(aa, w2.y, a23);
            }
            float v0, v1, v2, v3;
            unpack2(a01, v0, v1); unpack2(a23, v2, v3);
            sNT[(f0+0)*33 + n] = v0; sNT[(f0+1)*33 + n] = v1;
            sNT[(f0+2)*33 + n] = v2; sNT[(f0+3)*33 + n] = v3;
        }
        __syncthreads();
    }

    // ---- readout (scratch: bufA=t1, sBase=t2, sProj=t3, sBase=t4) ----
    {   // t1 = node @ W4a + b4a : [32][68]
        const int n = tid >> 3, f0 = (tid & 7) << 3;
        ull acc[4];
        acc[0] = *(const ull*)(p.b4a + f0);
        acc[1] = *(const ull*)(p.b4a + f0 + 2);
        acc[2] = *(const ull*)(p.b4a + f0 + 4);
        acc[3] = *(const ull*)(p.b4a + f0 + 6);
        #pragma unroll 4
        for (int k = 0; k < 32; ++k) {
            ull aa = dup2(sNT[k*33 + n]);
            ulonglong2 w0 = *(const ulonglong2*)(p.W4a + k*64 + f0);
            ulonglong2 w1 = *(const ulonglong2*)(p.W4a + k*64 + f0 + 4);
            acc[0] = fma2(aa, w0.x, acc[0]); acc[1] = fma2(aa, w0.y, acc[1]);
            acc[2] = fma2(aa, w1.x, acc[2]); acc[3] = fma2(aa, w1.y, acc[3]);
        }
        #pragma unroll
        for (int o = 0; o < 4; ++o) *(ull*)(bufA + n*68 + f0 + 2*o) = acc[o];
    }
    __syncthreads();
    {   // t2 = t1 @ W4b + b4b : [32][36] into sBase
        const int n = tid >> 3, f0 = (tid & 7) << 2;
        ull a01 = *(const ull*)(p.b4b + f0);
        ull a23 = *(const ull*)(p.b4b + f0 + 2);
        const float* r = bufA + n*68;
        #pragma unroll 4
        for (int k = 0; k < 64; ++k) {
            ull aa = dup2(r[k]);
            ulonglong2 w2 = *(const ulonglong2*)(p.W4b + k*32 + f0);
            a01 = fma2(aa, w2.x, a01);
            a23 = fma2(aa, w2.y, a23);
        }
        *(ull*)(sBase + n*36 + f0)     = a01;
        *(ull*)(sBase + n*36 + f0 + 2) = a23;
    }
    __syncthreads();
    {   // t3 = t2 @ W4c + b4c : [32][36] into sProj
        const int n = tid >> 3, f0 = (tid & 7) << 2;
        ull a01 = *(const ull*)(p.b4c + f0);
        ull a23 = *(const ull*)(p.b4c + f0 + 2);
        const float* r = sBase + n*36;
        #pragma unroll 4
        for (int k = 0; k < 32; ++k) {
            ull aa = dup2(r[k]);
            ulonglong2 w2 = *(const ulonglong2*)(p.W4c + k*32 + f0);
            a01 = fma2(aa, w2.x, a01);
            a23 = fma2(aa, w2.y, a23);
        }
        *(ull*)(sProj + n*36 + f0)     = a01;
        *(ull*)(sProj + n*36 + f0 + 2) = a23;
    }
    __syncthreads();
    {   // t4 = t3 @ W5a + b5a : [32][18] into sBase
        const int n = tid >> 3, f0 = (tid & 7) << 1;
        float a0 = p.b5a[f0], a1 = p.b5a[f0 + 1];
        const float* r = sProj + n*36;
        #pragma unroll 8
        for (int k = 0; k < 32; ++k) {
            float a = r[k];
            a0 += a * p.W5a[k*16 + f0];
            a1 += a * p.W5a[k*16 + f0 + 1];
        }
        sBase[n*18 + f0]     = a0;
        sBase[n*18 + f0 + 1] = a1;
    }
    __syncthreads();
    if (tid < 64) {
        const int n = tid >> 1, col = tid & 1;
        float acc = p.b5b[col];
        const float* r = sBase + n*18;
        #pragma unroll
        for (int k = 0; k < 16; ++k) acc += r[k] * p.W5b[k*2 + col];
        if (col == 0) p.out[b*32 + n] = acc;
        else          p.out[32768 + b*32 + n] = 1.0f / acc;
    }
}

extern "C" void kernel_launch(void* const* d_in, const int* in_sizes, int n_in,
                              void* d_out, int out_size) {
    const int has_iter = (n_in >= 32) ? 1 : 0;
    const int base = has_iter ? 8 : 7;

    GnnParams p;
    p.node0 = (const float*)d_in[0];
    p.edge  = (const float*)d_in[1];
    p.h0    = (const float*)d_in[2];
    p.mean  = (const float*)d_in[3];
    p.vari  = (const float*)d_in[4];
    p.iterp = has_iter ? (const int*)d_in[7] : nullptr;
    p.W1a = (const float*)d_in[base+0];  p.b1a = (const float*)d_in[base+1];
    p.W2a = (const float*)d_in[base+2];  p.b2a = (const float*)d_in[base+3];
    p.W2b = (const float*)d_in[base+4];  p.b2b = (const float*)d_in[base+5];
    p.W2c = (const float*)d_in[base+6];  p.b2c = (const float*)d_in[base+7];
    p.Wih = (const float*)d_in[base+8];  p.Whh = (const float*)d_in[base+9];
    p.bih = (const float*)d_in[base+10]; p.bhh = (const float*)d_in[base+11];
    p.W3b = (const float*)d_in[base+12]; p.b3b = (const float*)d_in[base+13];
    p.W4a = (const float*)d_in[base+14]; p.b4a = (const float*)d_in[base+15];
    p.W4b = (const float*)d_in[base+16]; p.b4b = (const float*)d_in[base+17];
    p.W4c = (const float*)d_in[base+18]; p.b4c = (const float*)d_in[base+19];
    p.W5a = (const float*)d_in[base+20]; p.b5a = (const float*)d_in[base+21];
    p.W5b = (const float*)d_in[base+22]; p.b5b = (const float*)d_in[base+23];
    p.out = (float*)d_out;

    cudaFuncSetAttribute(gnn_kernel,
                         cudaFuncAttributeMaxDynamicSharedMemorySize,
                         SMEM_FLOATS * (int)sizeof(float));
    gnn_kernel<<<1024, NT, SMEM_FLOATS * sizeof(float)>>>(p);
}

// round 8
// speedup vs baseline: 1.4842x; 1.0282x over previous
#include <cuda_runtime.h>
#include <math.h>

#define NT 256
typedef unsigned long long ull;

// Shared layout (float offsets)
#define OFF_NT    0        // nodeT [32 feat][32 node] stride 33 = 1056
#define OFF_H     1056     // [32][65] = 2080
#define OFF_MI    3136     // [32][36] = 1152
#define OFF_EDGE  4288     // [992][2] = 1984
#define OFF_BASE  6272     // [32][66] = 2112
#define OFF_PROJ  8384     // [32][66] = 2112
#define OFF_A     10496    // staging W2a[0:64]+b2a (4160) / readout t1 (2176)
#define OFF_W2B2  14656    // W2b: 2048 floats
#define OFF_W2C2  16704    // W2c: 1024 floats
#define OFF_W45S  17728    // W2a rows 64,65: 128 floats
#define OFF_B2B   17856    // 32
#define OFF_B2C   17888    // 32
#define SMEM_FLOATS 17920  // 71,680 B

__device__ __forceinline__ float gelu_f(float x) {
    return 0.5f * x * (1.0f + erff(x * 0.7071067811865476f));
}
__device__ __forceinline__ float sigm_f(float x) {
    return 1.0f / (1.0f + __expf(-x));
}
__device__ __forceinline__ ull pack2(float lo, float hi) {
    ull r; asm("mov.b64 %0, {%1, %2};" : "=l"(r) : "f"(lo), "f"(hi)); return r;
}
__device__ __forceinline__ ull dup2(float x) { return pack2(x, x); }
__device__ __forceinline__ void unpack2(ull v, float& lo, float& hi) {
    asm("mov.b64 {%0, %1}, %2;" : "=f"(lo), "=f"(hi) : "l"(v));
}
__device__ __forceinline__ ull fma2(ull a, ull b, ull c) {
    ull d; asm("fma.rn.f32x2 %0, %1, %2, %3;" : "=l"(d) : "l"(a), "l"(b), "l"(c));
    return d;
}
__device__ __forceinline__ ull add2(ull a, ull b) {
    ull d; asm("add.rn.f32x2 %0, %1, %2;" : "=l"(d) : "l"(a), "l"(b));
    return d;
}
__device__ __forceinline__ ull shflxor64(ull v, int m) {
    unsigned lo = (unsigned)v, hi = (unsigned)(v >> 32);
    lo = __shfl_xor_sync(0xffffffffu, lo, m);
    hi = __shfl_xor_sync(0xffffffffu, hi, m);
    return ((ull)hi << 32) | lo;
}

struct GnnParams {
    const float *node0, *edge, *h0, *mean, *vari;
    const int   *iterp;
    const float *W1a, *b1a, *W2a, *b2a, *W2b, *b2b, *W2c, *b2c;
    const float *Wih, *Whh, *bih, *bhh, *W3b, *b3b;
    const float *W4a, *b4a, *W4b, *b4b, *W4c, *b4c, *W5a, *b5a, *W5b, *b5b;
    float *out;
};

__global__ __launch_bounds__(NT, 1)
void gnn_kernel(GnnParams p) {
    extern __shared__ float sm[];
    const int tid  = threadIdx.x;
    const int b    = blockIdx.x;
    const int warp = tid >> 5, lane = tid & 31;

    float* sNT   = sm + OFF_NT;
    float* sH    = sm + OFF_H;     // stride 65
    float* sMi   = sm + OFF_MI;    // stride 36
    float* sEdge = sm + OFF_EDGE;
    float* sBase = sm + OFF_BASE;  // stride 66
    float* sProj = sm + OFF_PROJ;  // stride 66
    float* bufA  = sm + OFF_A;
    const ull* wB   = (const ull*)(sm + OFF_W2B2);
    const ull* wC   = (const ull*)(sm + OFF_W2C2);
    const ull* w45u = (const ull*)(sm + OFF_W45S);
    const ull* bB   = (const ull*)(sm + OFF_B2B);
    const ull* bC   = (const ull*)(sm + OFF_B2C);

    // ---- init copies (once) ----
    for (int i = tid; i < 992*2; i += NT) sEdge[i] = p.edge[b*1984 + i];
    for (int i = tid; i < 32*64; i += NT) {
        int n = i >> 6, k = i & 63;
        sH[n*65 + k] = p.h0[b*2048 + i];
    }
    for (int i = tid; i < 2048;  i += NT) sm[OFF_W2B2 + i] = p.W2b[i];
    for (int i = tid; i < 1024;  i += NT) sm[OFF_W2C2 + i] = p.W2c[i];
    for (int i = tid; i < 128;   i += NT) sm[OFF_W45S + i] = p.W2a[64*64 + i];
    for (int i = tid; i < 32;    i += NT) {
        sm[OFF_B2B + i] = p.b2b[i];
        sm[OFF_B2C + i] = p.b2c[i];
    }
    if (tid < 32) {
        sMi[tid*36 + 32] = p.mean[b*32 + tid];
        sMi[tid*36 + 33] = 1.0f / p.vari[b*32 + tid];
    }
    for (int i = tid; i < 1024; i += NT) sBase[i] = p.node0[b*1024 + i];
    for (int i = tid; i < 4096; i += NT) bufA[i] = p.W2a[i];
    for (int i = tid + 4096; i < 4160; i += NT) bufA[i] = p.b2a[i - 4096];
    __syncthreads();

    // ---- node = node0 @ W1a + b1a (write transposed into sNT) ----
    {
        const int n = tid >> 3, f0 = (tid & 7) << 2;
        float a0 = p.b1a[f0], a1 = p.b1a[f0+1], a2 = p.b1a[f0+2], a3 = p.b1a[f0+3];
        const float* r = sBase + n*32;
        #pragma unroll 8
        for (int k = 0; k < 32; ++k) {
            float a = r[k];
            float4 w = *(const float4*)(p.W1a + k*32 + f0);
            a0 += a*w.x; a1 += a*w.y; a2 += a*w.z; a3 += a*w.w;
        }
        sNT[(f0+0)*33 + n] = a0; sNT[(f0+1)*33 + n] = a1;
        sNT[(f0+2)*33 + n] = a2; sNT[(f0+3)*33 + n] = a3;
    }
    __syncthreads();

    const int iters = p.iterp ? *p.iterp : 3;

    for (int it = 0; it < iters; ++it) {
        // ---- base = node@W2a[0:32]+b2a ; proj = node@W2a[32:64] ----
        {
            const int n = tid >> 3, c0 = (tid & 7) << 3;
            ull bacc[4], pacc[4];
            {
                ulonglong2 b0 = *(const ulonglong2*)(bufA + 4096 + c0);
                ulonglong2 b1 = *(const ulonglong2*)(bufA + 4096 + c0 + 4);
                bacc[0]=b0.x; bacc[1]=b0.y; bacc[2]=b1.x; bacc[3]=b1.y;
            }
            const ull z = dup2(0.0f);
            #pragma unroll
            for (int o = 0; o < 4; ++o) pacc[o] = z;
            #pragma unroll 4
            for (int k = 0; k < 32; ++k) {
                ull aa = dup2(sNT[k*33 + n]);
                ulonglong2 wb0 = *(const ulonglong2*)(bufA + k*64 + c0);
                ulonglong2 wb1 = *(const ulonglong2*)(bufA + k*64 + c0 + 4);
                ulonglong2 wp0 = *(const ulonglong2*)(bufA + (32+k)*64 + c0);
                ulonglong2 wp1 = *(const ulonglong2*)(bufA + (32+k)*64 + c0 + 4);
                bacc[0] = fma2(aa, wb0.x, bacc[0]); bacc[1] = fma2(aa, wb0.y, bacc[1]);
                bacc[2] = fma2(aa, wb1.x, bacc[2]); bacc[3] = fma2(aa, wb1.y, bacc[3]);
                pacc[0] = fma2(aa, wp0.x, pacc[0]); pacc[1] = fma2(aa, wp0.y, pacc[1]);
                pacc[2] = fma2(aa, wp1.x, pacc[2]); pacc[3] = fma2(aa, wp1.y, pacc[3]);
            }
            #pragma unroll
            for (int o = 0; o < 4; ++o) {
                *(ull*)(sBase + n*66 + c0 + 2*o) = bacc[o];
                *(ull*)(sProj + n*66 + c0 + 2*o) = pacc[o];
            }
        }
        __syncthreads();

        // ---- edge phase: warp = node i, lane = edge q; register-resident ----
        for (int pass = 0; pass < 4; ++pass) {
            const int i = pass * 8 + warp;
            const int q = (lane < 31) ? lane : 30;
            const int j = q + (q >= i);
            const ull ev = *(const ull*)(sEdge + (i*31 + q)*2);
            float e0f, e1f; unpack2(ev, e0f, e1f);
            const ull e0d = dup2(e0f), e1d = dup2(e1f);
            const float* prj = sProj + j*66;
            const float* bas = sBase + i*66;

            ull acc[16];
            #pragma unroll
            for (int cp = 0; cp < 16; ++cp) acc[cp] = bB[cp];

            #pragma unroll 4
            for (int t = 0; t < 32; ++t) {
                ull bst = *(const ull*)(bas + 2*t);   // warp-uniform: broadcast
                ull pr2 = *(const ull*)(prj + 2*t);
                ull u = add2(bst, pr2);
                u = fma2(e0d, w45u[t], u);
                u = fma2(e1d, w45u[32 + t], u);
                float g0, g1; unpack2(u, g0, g1);
                ull a0 = dup2(gelu_f(g0)), a1 = dup2(gelu_f(g1));
                #pragma unroll
                for (int cp2 = 0; cp2 < 8; ++cp2) {
                    ulonglong2 w0 = *(const ulonglong2*)(wB + (2*t)*16 + 2*cp2);
                    ulonglong2 w1 = *(const ulonglong2*)(wB + (2*t+1)*16 + 2*cp2);
                    acc[2*cp2]   = fma2(a0, w0.x, acc[2*cp2]);
                    acc[2*cp2+1] = fma2(a0, w0.y, acc[2*cp2+1]);
                    acc[2*cp2]   = fma2(a1, w1.x, acc[2*cp2]);
                    acc[2*cp2+1] = fma2(a1, w1.y, acc[2*cp2+1]);
                }
            }

            // layer 3 from registers
            ull macc[16];
            #pragma unroll
            for (int cp = 0; cp < 16; ++cp) macc[cp] = bC[cp];
            #pragma unroll 4
            for (int cqp = 0; cqp < 16; ++cqp) {
                float v0, v1; unpack2(acc[cqp], v0, v1);
                ull a0 = dup2(gelu_f(v0)), a1 = dup2(gelu_f(v1));
                #pragma unroll
                for (int cp2 = 0; cp2 < 8; ++cp2) {
                    ulonglong2 w0 = *(const ulonglong2*)(wC + (2*cqp)*16 + 2*cp2);
                    ulonglong2 w1 = *(const ulonglong2*)(wC + (2*cqp+1)*16 + 2*cp2);
                    macc[2*cp2]   = fma2(a0, w0.x, macc[2*cp2]);
                    macc[2*cp2+1] = fma2(a0, w0.y, macc[2*cp2+1]);
                    macc[2*cp2]   = fma2(a1, w1.x, macc[2*cp2]);
                    macc[2*cp2+1] = fma2(a1, w1.y, macc[2*cp2+1]);
                }
            }

            // gelu + mask dummy lane
            #pragma unroll
            for (int cp = 0; cp < 16; ++cp) {
                float v0, v1; unpack2(macc[cp], v0, v1);
                macc[cp] = (lane < 31) ? pack2(gelu_f(v0), gelu_f(v1)) : 0ULL;
            }
            // Butterfly transpose-reduce: lane ends with the full edge-sum of
            // element bitrev4(lane&15) in macc[0] (static register index).
            #pragma unroll
            for (int s = 0; s < 4; ++s) {
                const int off = 1 << s;
                const int h = 8 >> s;
                const bool keep_low = ((lane >> s) & 1) == 0;
                #pragma unroll
                for (int r = 0; r < 8; ++r) {
                    if (r < h) {
                        ull send = keep_low ? macc[r + h] : macc[r];
                        ull recv = shflxor64(send, off);
                        ull mine = keep_low ? macc[r] : macc[r + h];
                        macc[r] = add2(mine, recv);
                    }
                }
            }
            macc[0] = add2(macc[0], shflxor64(macc[0], 16));
            if (lane < 16) {
                const int e = ((lane & 1) << 3) | (((lane >> 1) & 1) << 2) |
                              (((lane >> 2) & 1) << 1) | ((lane >> 3) & 1);
                *(ull*)(sMi + i*36 + 2*e) = macc[0];
            }
        }
        __syncthreads();

        // ---- GRU cell (GELU new gate), packed col-pairs ----
        {
            const int n  = tid >> 3;
            const int c0 = (tid & 7) << 3;
            ull ar[4], az[4], an_[4], hn_[4];
            #pragma unroll
            for (int o = 0; o < 4; ++o) {
                ull bi_r = *(const ull*)(p.bih + c0 + 2*o);
                ull bh_r = *(const ull*)(p.bhh + c0 + 2*o);
                ull bi_z = *(const ull*)(p.bih + 64 + c0 + 2*o);
                ull bh_z = *(const ull*)(p.bhh + 64 + c0 + 2*o);
                ar[o]  = add2(bi_r, bh_r);
                az[o]  = add2(bi_z, bh_z);
                an_[o] = *(const ull*)(p.bih + 128 + c0 + 2*o);
                hn_[o] = *(const ull*)(p.bhh + 128 + c0 + 2*o);
            }
            const float* mi = sMi + n*36;
            #pragma unroll 2
            for (int k = 0; k < 34; ++k) {
                ull aa = dup2(mi[k]);
                const float* w = p.Wih + k*192;
                ulonglong2 r01 = *(const ulonglong2*)(w + c0);
                ulonglong2 r23 = *(const ulonglong2*)(w + c0 + 4);
                ulonglong2 z01 = *(const ulonglong2*)(w + 64 + c0);
                ulonglong2 z23 = *(const ulonglong2*)(w + 64 + c0 + 4);
                ulonglong2 n01 = *(const ulonglong2*)(w + 128 + c0);
                ulonglong2 n23 = *(const ulonglong2*)(w + 128 + c0 + 4);
                ar[0]=fma2(aa,r01.x,ar[0]); ar[1]=fma2(aa,r01.y,ar[1]);
                ar[2]=fma2(aa,r23.x,ar[2]); ar[3]=fma2(aa,r23.y,ar[3]);
                az[0]=fma2(aa,z01.x,az[0]); az[1]=fma2(aa,z01.y,az[1]);
                az[2]=fma2(aa,z23.x,az[2]); az[3]=fma2(aa,z23.y,az[3]);
                an_[0]=fma2(aa,n01.x,an_[0]); an_[1]=fma2(aa,n01.y,an_[1]);
                an_[2]=fma2(aa,n23.x,an_[2]); an_[3]=fma2(aa,n23.y,an_[3]);
            }
            const float* hv = sH + n*65;
            #pragma unroll 2
            for (int k = 0; k < 64; ++k) {
                ull aa = dup2(hv[k]);
                const float* w = p.Whh + k*192;
                ulonglong2 r01 = *(const ulonglong2*)(w + c0);
                ulonglong2 r23 = *(const ulonglong2*)(w + c0 + 4);
                ulonglong2 z01 = *(const ulonglong2*)(w + 64 + c0);
                ulonglong2 z23 = *(const ulonglong2*)(w + 64 + c0 + 4);
                ulonglong2 n01 = *(const ulonglong2*)(w + 128 + c0);
                ulonglong2 n23 = *(const ulonglong2*)(w + 128 + c0 + 4);
                ar[0]=fma2(aa,r01.x,ar[0]); ar[1]=fma2(aa,r01.y,ar[1]);
                ar[2]=fma2(aa,r23.x,ar[2]); ar[3]=fma2(aa,r23.y,ar[3]);
                az[0]=fma2(aa,z01.x,az[0]); az[1]=fma2(aa,z01.y,az[1]);
                az[2]=fma2(aa,z23.x,az[2]); az[3]=fma2(aa,z23.y,az[3]);
                hn_[0]=fma2(aa,n01.x,hn_[0]); hn_[1]=fma2(aa,n01.y,hn_[1]);
                hn_[2]=fma2(aa,n23.x,hn_[2]); hn_[3]=fma2(aa,n23.y,hn_[3]);
            }
            float hnew[8];
            #pragma unroll
            for (int o = 0; o < 4; ++o) {
                float r0, r1, z0, z1, in0, in1, hn0, hn1;
                unpack2(ar[o], r0, r1);
                unpack2(az[o], z0, z1);
                unpack2(an_[o], in0, in1);
                unpack2(hn_[o], hn0, hn1);
                float rr0 = sigm_f(r0), rr1 = sigm_f(r1);
                float zz0 = sigm_f(z0), zz1 = sigm_f(z1);
                float g0 = gelu_f(in0 + rr0 * hn0);
                float g1 = gelu_f(in1 + rr1 * hn1);
                hnew[2*o]   = (1.0f - zz0) * g0 + zz0 * hv[c0 + 2*o];
                hnew[2*o+1] = (1.0f - zz1) * g1 + zz1 * hv[c0 + 2*o + 1];
            }
            __syncthreads();
            #pragma unroll
            for (int o = 0; o < 8; ++o) sH[n*65 + c0 + o] = hnew[o];
        }
        __syncthreads();

        // ---- node = h @ W3b + b3b  (packed, write transposed into sNT) ----
        {
            const int n = tid >> 3, f0 = (tid & 7) << 2;
            ull a01 = *(const ull*)(p.b3b + f0);
            ull a23 = *(const ull*)(p.b3b + f0 + 2);
            const float* hv = sH + n*65;
            #pragma unroll 4
            for (int k = 0; k < 64; ++k) {
                ull aa = dup2(hv[k]);
                ulonglong2 w2 = *(const ulonglong2*)(p.W3b + k*32 + f0);
                a01 = fma2(aa, w2.x, a01);
                a23 = fma2(aa, w2.y, a23);
            }
            float v0, v1, v2, v3;
            unpack2(a01, v0, v1); unpack2(a23, v2, v3);
            sNT[(f0+0)*33 + n] = v0; sNT[(f0+1)*33 + n] = v1;
            sNT[(f0+2)*33 + n] = v2; sNT[(f0+3)*33 + n] = v3;
        }
        __syncthreads();
    }

    // ---- readout (scratch: bufA=t1, sBase=t2, sProj=t3, sBase=t4) ----
    {   // t1 = node @ W4a + b4a : [32][68]
        const int n = tid >> 3, f0 = (tid & 7) << 3;
        ull acc[4];
        acc[0] = *(const ull*)(p.b4a + f0);
        acc[1] = *(const ull*)(p.b4a + f0 + 2);
        acc[2] = *(const ull*)(p.b4a + f0 + 4);
        acc[3] = *(const ull*)(p.b4a + f0 + 6);
        #pragma unroll 4
        for (int k = 0; k < 32; ++k) {
            ull aa = dup2(sNT[k*33 + n]);
            ulonglong2 w0 = *(const ulonglong2*)(p.W4a + k*64 + f0);
            ulonglong2 w1 = *(const ulonglong2*)(p.W4a + k*64 + f0 + 4);
            acc[0] = fma2(aa, w0.x, acc[0]); acc[1] = fma2(aa, w0.y, acc[1]);
            acc[2] = fma2(aa, w1.x, acc[2]); acc[3] = fma2(aa, w1.y, acc[3]);
        }
        #pragma unroll
        for (int o = 0; o < 4; ++o) *(ull*)(bufA + n*68 + f0 + 2*o) = acc[o];
    }
    __syncthreads();
    {   // t2 = t1 @ W4b + b4b : [32][36] into sBase
        const int n = tid >> 3, f0 = (tid & 7) << 2;
        ull a01 = *(const ull*)(p.b4b + f0);
        ull a23 = *(const ull*)(p.b4b + f0 + 2);
        const float* r = bufA + n*68;
        #pragma unroll 4
        for (int k = 0; k < 64; ++k) {
            ull aa = dup2(r[k]);
            ulonglong2 w2 = *(const ulonglong2*)(p.W4b + k*32 + f0);
            a01 = fma2(aa, w2.x, a01);
            a23 = fma2(aa, w2.y, a23);
        }
        *(ull*)(sBase + n*36 + f0)     = a01;
        *(ull*)(sBase + n*36 + f0 + 2) = a23;
    }
    __syncthreads();
    {   // t3 = t2 @ W4c + b4c : [32][36] into sProj
        const int n = tid >> 3, f0 = (tid & 7) << 2;
        ull a01 = *(const ull*)(p.b4c + f0);
        ull a23 = *(const ull*)(p.b4c + f0 + 2);
        const float* r = sBase + n*36;
        #pragma unroll 4
        for (int k = 0; k < 32; ++k) {
            ull aa = dup2(r[k]);
            ulonglong2 w2 = *(const ulonglong2*)(p.W4c + k*32 + f0);
            a01 = fma2(aa, w2.x, a01);
            a23 = fma2(aa, w2.y, a23);
        }
        *(ull*)(sProj + n*36 + f0)     = a01;
        *(ull*)(sProj + n*36 + f0 + 2) = a23;
    }
    __syncthreads();
    {   // t4 = t3 @ W5a + b5a : [32][18] into sBase
        const int n = tid >> 3, f0 = (tid & 7) << 1;
        float a0 = p.b5a[f0], a1 = p.b5a[f0 + 1];
        const float* r = sProj + n*36;
        #pragma unroll 8
        for (int k = 0; k < 32; ++k) {
            float a = r[k];
            a0 += a * p.W5a[k*16 + f0];
            a1 += a * p.W5a[k*16 + f0 + 1];
        }
        sBase[n*18 + f0]     = a0;
        sBase[n*18 + f0 + 1] = a1;
    }
    __syncthreads();
    if (tid < 64) {
        const int n = tid >> 1, col = tid & 1;
        float acc = p.b5b[col];
        const float* r = sBase + n*18;
        #pragma unroll
        for (int k = 0; k < 16; ++k) acc += r[k] * p.W5b[k*2 + col];
        if (col == 0) p.out[b*32 + n] = acc;
        else          p.out[32768 + b*32 + n] = 1.0f / acc;
    }
}

extern "C" void kernel_launch(void* const* d_in, const int* in_sizes, int n_in,
                              void* d_out, int out_size) {
    const int has_iter = (n_in >= 32) ? 1 : 0;
    const int base = has_iter ? 8 : 7;

    GnnParams p;
    p.node0 = (const float*)d_in[0];
    p.edge  = (const float*)d_in[1];
    p.h0    = (const float*)d_in[2];
    p.mean  = (const float*)d_in[3];
    p.vari  = (const float*)d_in[4];
    p.iterp = has_iter ? (const int*)d_in[7] : nullptr;
    p.W1a = (const float*)d_in[base+0];  p.b1a = (const float*)d_in[base+1];
    p.W2a = (const float*)d_in[base+2];  p.b2a = (const float*)d_in[base+3];
    p.W2b = (const float*)d_in[base+4];  p.b2b = (const float*)d_in[base+5];
    p.W2c = (const float*)d_in[base+6];  p.b2c = (const float*)d_in[base+7];
    p.Wih = (const float*)d_in[base+8];  p.Whh = (const float*)d_in[base+9];
    p.bih = (const float*)d_in[base+10]; p.bhh = (const float*)d_in[base+11];
    p.W3b = (const float*)d_in[base+12]; p.b3b = (const float*)d_in[base+13];
    p.W4a = (const float*)d_in[base+14]; p.b4a = (const float*)d_in[base+15];
    p.W4b = (const float*)d_in[base+16]; p.b4b = (const float*)d_in[base+17];
    p.W4c = (const float*)d_in[base+18]; p.b4c = (const float*)d_in[base+19];
    p.W5a = (const float*)d_in[base+20]; p.b5a = (const float*)d_in[base+21];
    p.W5b = (const float*)d_in[base+22]; p.b5b = (const float*)d_in[base+23];
    p.out = (float*)d_out;

    cudaFuncSetAttribute(gnn_kernel,
                         cudaFuncAttributeMaxDynamicSharedMemorySize,
                         SMEM_FLOATS * (int)sizeof(float));
    gnn_kernel<<<1024, NT, SMEM_FLOATS * sizeof(float)>>>(p);
}

// round 9
// speedup vs baseline: 1.6378x; 1.1034x over previous
#include <cuda_runtime.h>
#include <math.h>

#define NT 256
typedef unsigned long long ull;

// Shared layout (float offsets)
#define OFF_NT    0        // nodeT [32 feat][32 node] stride 33 = 1056
#define OFF_H     1056     // [32][65] = 2080
#define OFF_MI    3136     // [32][36] = 1152
#define OFF_EDGE  4288     // [992][2] = 1984
#define OFF_BASE  6272     // [32][66] = 2112
#define OFF_PROJ  8384     // [32][66] = 2112
#define OFF_A     10496    // staging W2a[0:64]+b2a (4160) / readout t1 (2176)
#define OFF_W2B2  14656    // W2b: 2048 floats
#define OFF_W2C2  16704    // W2c: 1024 floats
#define OFF_W45S  17728    // W2a rows 64,65: 128 floats
#define OFF_B2B   17856    // 32
#define OFF_B2C   17888    // 32
#define SMEM_FLOATS 17920  // 71,680 B

// ---- branch-free, MUFU-free GELU (erf via A&S 7.1.26, |eps|<=1.5e-7) ----
__device__ __forceinline__ float gelu_f(float x) {
    float xc = fminf(fmaxf(x, -5.65f), 5.65f);   // keep s in [-4,4]
    float s  = xc * 0.7071067811865476f;
    float a  = fabsf(s);
    // t = 1/(1+p*a), p = 0.3275911 : Newton reciprocal (no MUFU)
    float v  = fmaf(0.3275911f, a, 1.0f);        // v in [1, 2.31]
    float r  = fmaf(-0.4329f, v, 1.3744f);       // minimax linear seed
    r = r * (2.0f - v * r);
    r = r * (2.0f - v * r);
    r = r * (2.0f - v * r);
    // e^{-a^2} via 2^k * 2^f (no MUFU)
    float u  = a * a;                             // [0,16]
    float y  = u * -1.4426950408889634f;          // [-23.1, 0]
    float tb = y + 12582912.0f;                   // 1.5*2^23 magic
    int   ki = __float_as_int(tb) - 0x4B400000;   // round(y)
    float kf = tb - 12582912.0f;
    float f  = y - kf;                            // [-0.5, 0.5]
    float pe = 1.33335581e-3f;                    // ln2^5/120
    pe = fmaf(pe, f, 9.61812911e-3f);             // ln2^4/24
    pe = fmaf(pe, f, 5.55041087e-2f);             // ln2^3/6
    pe = fmaf(pe, f, 2.40226507e-1f);             // ln2^2/2
    pe = fmaf(pe, f, 6.93147181e-1f);             // ln2
    pe = fmaf(pe, f, 1.0f);
    float ex = pe * __int_as_float((ki + 127) << 23);
    // A&S polynomial in t=r
    float q = 1.061405429f;
    q = fmaf(q, r, -1.453152027f);
    q = fmaf(q, r, 1.421413741f);
    q = fmaf(q, r, -0.284496736f);
    q = fmaf(q, r, 0.254829592f);
    q = q * r;
    float E = fmaf(-q, ex, 1.0f);                 // erf(|s|)
    E = copysignf(E, s);
    return 0.5f * x * (1.0f + E);
}
__device__ __forceinline__ float sigm_f(float x) {
    return 1.0f / (1.0f + __expf(-x));
}
__device__ __forceinline__ ull pack2(float lo, float hi) {
    ull r; asm("mov.b64 %0, {%1, %2};" : "=l"(r) : "f"(lo), "f"(hi)); return r;
}
__device__ __forceinline__ ull dup2(float x) { return pack2(x, x); }
__device__ __forceinline__ void unpack2(ull v, float& lo, float& hi) {
    asm("mov.b64 {%0, %1}, %2;" : "=f"(lo), "=f"(hi) : "l"(v));
}
__device__ __forceinline__ ull fma2(ull a, ull b, ull c) {
    ull d; asm("fma.rn.f32x2 %0, %1, %2, %3;" : "=l"(d) : "l"(a), "l"(b), "l"(c));
    return d;
}
__device__ __forceinline__ ull add2(ull a, ull b) {
    ull d; asm("add.rn.f32x2 %0, %1, %2;" : "=l"(d) : "l"(a), "l"(b));
    return d;
}
__device__ __forceinline__ ull shflxor64(ull v, int m) {
    unsigned lo = (unsigned)v, hi = (unsigned)(v >> 32);
    lo = __shfl_xor_sync(0xffffffffu, lo, m);
    hi = __shfl_xor_sync(0xffffffffu, hi, m);
    return ((ull)hi << 32) | lo;
}

struct GnnParams {
    const float *node0, *edge, *h0, *mean, *vari;
    const int   *iterp;
    const float *W1a, *b1a, *W2a, *b2a, *W2b, *b2b, *W2c, *b2c;
    const float *Wih, *Whh, *bih, *bhh, *W3b, *b3b;
    const float *W4a, *b4a, *W4b, *b4b, *W4c, *b4c, *W5a, *b5a, *W5b, *b5b;
    float *out;
};

__global__ __launch_bounds__(NT, 1)
void gnn_kernel(GnnParams p) {
    extern __shared__ float sm[];
    const int tid  = threadIdx.x;
    const int b    = blockIdx.x;
    const int warp = tid >> 5, lane = tid & 31;

    float* sNT   = sm + OFF_NT;
    float* sH    = sm + OFF_H;     // stride 65
    float* sMi   = sm + OFF_MI;    // stride 36
    float* sEdge = sm + OFF_EDGE;
    float* sBase = sm + OFF_BASE;  // stride 66
    float* sProj = sm + OFF_PROJ;  // stride 66
    float* bufA  = sm + OFF_A;
    const ull* wB   = (const ull*)(sm + OFF_W2B2);
    const ull* wC   = (const ull*)(sm + OFF_W2C2);
    const ull* w45u = (const ull*)(sm + OFF_W45S);
    const ull* bB   = (const ull*)(sm + OFF_B2B);
    const ull* bC   = (const ull*)(sm + OFF_B2C);

    // ---- init copies (once) ----
    for (int i = tid; i < 992*2; i += NT) sEdge[i] = p.edge[b*1984 + i];
    for (int i = tid; i < 32*64; i += NT) {
        int n = i >> 6, k = i & 63;
        sH[n*65 + k] = p.h0[b*2048 + i];
    }
    for (int i = tid; i < 2048;  i += NT) sm[OFF_W2B2 + i] = p.W2b[i];
    for (int i = tid; i < 1024;  i += NT) sm[OFF_W2C2 + i] = p.W2c[i];
    for (int i = tid; i < 128;   i += NT) sm[OFF_W45S + i] = p.W2a[64*64 + i];
    for (int i = tid; i < 32;    i += NT) {
        sm[OFF_B2B + i] = p.b2b[i];
        sm[OFF_B2C + i] = p.b2c[i];
    }
    if (tid < 32) {
        sMi[tid*36 + 32] = p.mean[b*32 + tid];
        sMi[tid*36 + 33] = 1.0f / p.vari[b*32 + tid];
    }
    for (int i = tid; i < 1024; i += NT) sBase[i] = p.node0[b*1024 + i];
    for (int i = tid; i < 4096; i += NT) bufA[i] = p.W2a[i];
    for (int i = tid + 4096; i < 4160; i += NT) bufA[i] = p.b2a[i - 4096];
    __syncthreads();

    // ---- node = node0 @ W1a + b1a (write transposed into sNT) ----
    {
        const int n = tid >> 3, f0 = (tid & 7) << 2;
        float a0 = p.b1a[f0], a1 = p.b1a[f0+1], a2 = p.b1a[f0+2], a3 = p.b1a[f0+3];
        const float* r = sBase + n*32;
        #pragma unroll 8
        for (int k = 0; k < 32; ++k) {
            float a = r[k];
            float4 w = *(const float4*)(p.W1a + k*32 + f0);
            a0 += a*w.x; a1 += a*w.y; a2 += a*w.z; a3 += a*w.w;
        }
        sNT[(f0+0)*33 + n] = a0; sNT[(f0+1)*33 + n] = a1;
        sNT[(f0+2)*33 + n] = a2; sNT[(f0+3)*33 + n] = a3;
    }
    __syncthreads();

    const int iters = p.iterp ? *p.iterp : 3;

    for (int it = 0; it < iters; ++it) {
        // ---- base = node@W2a[0:32]+b2a ; proj = node@W2a[32:64] ----
        {
            const int n = tid >> 3, c0 = (tid & 7) << 3;
            ull bacc[4], pacc[4];
            {
                ulonglong2 b0 = *(const ulonglong2*)(bufA + 4096 + c0);
                ulonglong2 b1 = *(const ulonglong2*)(bufA + 4096 + c0 + 4);
                bacc[0]=b0.x; bacc[1]=b0.y; bacc[2]=b1.x; bacc[3]=b1.y;
            }
            const ull z = dup2(0.0f);
            #pragma unroll
            for (int o = 0; o < 4; ++o) pacc[o] = z;
            #pragma unroll 4
            for (int k = 0; k < 32; ++k) {
                ull aa = dup2(sNT[k*33 + n]);
                ulonglong2 wb0 = *(const ulonglong2*)(bufA + k*64 + c0);
                ulonglong2 wb1 = *(const ulonglong2*)(bufA + k*64 + c0 + 4);
                ulonglong2 wp0 = *(const ulonglong2*)(bufA + (32+k)*64 + c0);
                ulonglong2 wp1 = *(const ulonglong2*)(bufA + (32+k)*64 + c0 + 4);
                bacc[0] = fma2(aa, wb0.x, bacc[0]); bacc[1] = fma2(aa, wb0.y, bacc[1]);
                bacc[2] = fma2(aa, wb1.x, bacc[2]); bacc[3] = fma2(aa, wb1.y, bacc[3]);
                pacc[0] = fma2(aa, wp0.x, pacc[0]); pacc[1] = fma2(aa, wp0.y, pacc[1]);
                pacc[2] = fma2(aa, wp1.x, pacc[2]); pacc[3] = fma2(aa, wp1.y, pacc[3]);
            }
            #pragma unroll
            for (int o = 0; o < 4; ++o) {
                *(ull*)(sBase + n*66 + c0 + 2*o) = bacc[o];
                *(ull*)(sProj + n*66 + c0 + 2*o) = pacc[o];
            }
        }
        __syncthreads();

        // ---- edge phase: warp = node i, lane = edge q; register-resident ----
        for (int pass = 0; pass < 4; ++pass) {
            const int i = pass * 8 + warp;
            const int q = (lane < 31) ? lane : 30;
            const int j = q + (q >= i);
            const ull ev = *(const ull*)(sEdge + (i*31 + q)*2);
            float e0f, e1f; unpack2(ev, e0f, e1f);
            const ull e0d = dup2(e0f), e1d = dup2(e1f);
            const float* prj = sProj + j*66;
            const float* bas = sBase + i*66;

            ull acc[16];
            #pragma unroll
            for (int cp = 0; cp < 16; ++cp) acc[cp] = bB[cp];

            #pragma unroll 4
            for (int t = 0; t < 32; ++t) {
                ull bst = *(const ull*)(bas + 2*t);   // warp-uniform: broadcast
                ull pr2 = *(const ull*)(prj + 2*t);
                ull u = add2(bst, pr2);
                u = fma2(e0d, w45u[t], u);
                u = fma2(e1d, w45u[32 + t], u);
                float g0, g1; unpack2(u, g0, g1);
                ull a0 = dup2(gelu_f(g0)), a1 = dup2(gelu_f(g1));
                #pragma unroll
                for (int cp2 = 0; cp2 < 8; ++cp2) {
                    ulonglong2 w0 = *(const ulonglong2*)(wB + (2*t)*16 + 2*cp2);
                    ulonglong2 w1 = *(const ulonglong2*)(wB + (2*t+1)*16 + 2*cp2);
                    acc[2*cp2]   = fma2(a0, w0.x, acc[2*cp2]);
                    acc[2*cp2+1] = fma2(a0, w0.y, acc[2*cp2+1]);
                    acc[2*cp2]   = fma2(a1, w1.x, acc[2*cp2]);
                    acc[2*cp2+1] = fma2(a1, w1.y, acc[2*cp2+1]);
                }
            }

            // layer 3 from registers
            ull macc[16];
            #pragma unroll
            for (int cp = 0; cp < 16; ++cp) macc[cp] = bC[cp];
            #pragma unroll 4
            for (int cqp = 0; cqp < 16; ++cqp) {
                float v0, v1; unpack2(acc[cqp], v0, v1);
                ull a0 = dup2(gelu_f(v0)), a1 = dup2(gelu_f(v1));
                #pragma unroll
                for (int cp2 = 0; cp2 < 8; ++cp2) {
                    ulonglong2 w0 = *(const ulonglong2*)(wC + (2*cqp)*16 + 2*cp2);
                    ulonglong2 w1 = *(const ulonglong2*)(wC + (2*cqp+1)*16 + 2*cp2);
                    macc[2*cp2]   = fma2(a0, w0.x, macc[2*cp2]);
                    macc[2*cp2+1] = fma2(a0, w0.y, macc[2*cp2+1]);
                    macc[2*cp2]   = fma2(a1, w1.x, macc[2*cp2]);
                    macc[2*cp2+1] = fma2(a1, w1.y, macc[2*cp2+1]);
                }
            }

            // gelu + mask dummy lane
            #pragma unroll
            for (int cp = 0; cp < 16; ++cp) {
                float v0, v1; unpack2(macc[cp], v0, v1);
                macc[cp] = (lane < 31) ? pack2(gelu_f(v0), gelu_f(v1)) : 0ULL;
            }
            // Butterfly transpose-reduce: lane ends with the full edge-sum of
            // element bitrev4(lane&15) in macc[0] (static register index).
            #pragma unroll
            for (int s = 0; s < 4; ++s) {
                const int off = 1 << s;
                const int h = 8 >> s;
                const bool keep_low = ((lane >> s) & 1) == 0;
                #pragma unroll
                for (int r = 0; r < 8; ++r) {
                    if (r < h) {
                        ull send = keep_low ? macc[r + h] : macc[r];
                        ull recv = shflxor64(send, off);
                        ull mine = keep_low ? macc[r] : macc[r + h];
                        macc[r] = add2(mine, recv);
                    }
                }
            }
            macc[0] = add2(macc[0], shflxor64(macc[0], 16));
            if (lane < 16) {
                const int e = ((lane & 1) << 3) | (((lane >> 1) & 1) << 2) |
                              (((lane >> 2) & 1) << 1) | ((lane >> 3) & 1);
                *(ull*)(sMi + i*36 + 2*e) = macc[0];
            }
        }
        __syncthreads();

        // ---- GRU cell (GELU new gate), packed col-pairs ----
        {
            const int n  = tid >> 3;
            const int c0 = (tid & 7) << 3;
            ull ar[4], az[4], an_[4], hn_[4];
            #pragma unroll
            for (int o = 0; o < 4; ++o) {
                ull bi_r = *(const ull*)(p.bih + c0 + 2*o);
                ull bh_r = *(const ull*)(p.bhh + c0 + 2*o);
                ull bi_z = *(const ull*)(p.bih + 64 + c0 + 2*o);
                ull bh_z = *(const ull*)(p.bhh + 64 + c0 + 2*o);
                ar[o]  = add2(bi_r, bh_r);
                az[o]  = add2(bi_z, bh_z);
                an_[o] = *(const ull*)(p.bih + 128 + c0 + 2*o);
                hn_[o] = *(const ull*)(p.bhh + 128 + c0 + 2*o);
            }
            const float* mi = sMi + n*36;
            #pragma unroll 2
            for (int k = 0; k < 34; ++k) {
                ull aa = dup2(mi[k]);
                const float* w = p.Wih + k*192;
                ulonglong2 r01 = *(const ulonglong2*)(w + c0);
                ulonglong2 r23 = *(const ulonglong2*)(w + c0 + 4);
                ulonglong2 z01 = *(const ulonglong2*)(w + 64 + c0);
                ulonglong2 z23 = *(const ulonglong2*)(w + 64 + c0 + 4);
                ulonglong2 n01 = *(const ulonglong2*)(w + 128 + c0);
                ulonglong2 n23 = *(const ulonglong2*)(w + 128 + c0 + 4);
                ar[0]=fma2(aa,r01.x,ar[0]); ar[1]=fma2(aa,r01.y,ar[1]);
                ar[2]=fma2(aa,r23.x,ar[2]); ar[3]=fma2(aa,r23.y,ar[3]);
                az[0]=fma2(aa,z01.x,az[0]); az[1]=fma2(aa,z01.y,az[1]);
                az[2]=fma2(aa,z23.x,az[2]); az[3]=fma2(aa,z23.y,az[3]);
                an_[0]=fma2(aa,n01.x,an_[0]); an_[1]=fma2(aa,n01.y,an_[1]);
                an_[2]=fma2(aa,n23.x,an_[2]); an_[3]=fma2(aa,n23.y,an_[3]);
            }
            const float* hv = sH + n*65;
            #pragma unroll 2
            for (int k = 0; k < 64; ++k) {
                ull aa = dup2(hv[k]);
                const float* w = p.Whh + k*192;
                ulonglong2 r01 = *(const ulonglong2*)(w + c0);
                ulonglong2 r23 = *(const ulonglong2*)(w + c0 + 4);
                ulonglong2 z01 = *(const ulonglong2*)(w + 64 + c0);
                ulonglong2 z23 = *(const ulonglong2*)(w + 64 + c0 + 4);
                ulonglong2 n01 = *(const ulonglong2*)(w + 128 + c0);
                ulonglong2 n23 = *(const ulonglong2*)(w + 128 + c0 + 4);
                ar[0]=fma2(aa,r01.x,ar[0]); ar[1]=fma2(aa,r01.y,ar[1]);
                ar[2]=fma2(aa,r23.x,ar[2]); ar[3]=fma2(aa,r23.y,ar[3]);
                az[0]=fma2(aa,z01.x,az[0]); az[1]=fma2(aa,z01.y,az[1]);
                az[2]=fma2(aa,z23.x,az[2]); az[3]=fma2(aa,z23.y,az[3]);
                hn_[0]=fma2(aa,n01.x,hn_[0]); hn_[1]=fma2(aa,n01.y,hn_[1]);
                hn_[2]=fma2(aa,n23.x,hn_[2]); hn_[3]=fma2(aa,n23.y,hn_[3]);
            }
            float hnew[8];
            #pragma unroll
            for (int o = 0; o < 4; ++o) {
                float r0, r1, z0, z1, in0, in1, hn0, hn1;
                unpack2(ar[o], r0, r1);
                unpack2(az[o], z0, z1);
                unpack2(an_[o], in0, in1);
                unpack2(hn_[o], hn0, hn1);
                float rr0 = sigm_f(r0), rr1 = sigm_f(r1);
                float zz0 = sigm_f(z0), zz1 = sigm_f(z1);
                float g0 = gelu_f(in0 + rr0 * hn0);
                float g1 = gelu_f(in1 + rr1 * hn1);
                hnew[2*o]   = (1.0f - zz0) * g0 + zz0 * hv[c0 + 2*o];
                hnew[2*o+1] = (1.0f - zz1) * g1 + zz1 * hv[c0 + 2*o + 1];
            }
            __syncthreads();
            #pragma unroll
            for (int o = 0; o < 8; ++o) sH[n*65 + c0 + o] = hnew[o];
        }
        __syncthreads();

        // ---- node = h @ W3b + b3b  (packed, write transposed into sNT) ----
        {
            const int n = tid >> 3, f0 = (tid & 7) << 2;
            ull a01 = *(const ull*)(p.b3b + f0);
            ull a23 = *(const ull*)(p.b3b + f0 + 2);
            const float* hv = sH + n*65;
            #pragma unroll 4
            for (int k = 0; k < 64; ++k) {
                ull aa = dup2(hv[k]);
                ulonglong2 w2 = *(const ulonglong2*)(p.W3b + k*32 + f0);
                a01 = fma2(aa, w2.x, a01);
                a23 = fma2(aa, w2.y, a23);
            }
            float v0, v1, v2, v3;
            unpack2(a01, v0, v1); unpack2(a23, v2, v3);
            sNT[(f0+0)*33 + n] = v0; sNT[(f0+1)*33 + n] = v1;
            sNT[(f0+2)*33 + n] = v2; sNT[(f0+3)*33 + n] = v3;
        }
        __syncthreads();
    }

    // ---- readout (scratch: bufA=t1, sBase=t2, sProj=t3, sBase=t4) ----
    {   // t1 = node @ W4a + b4a : [32][68]
        const int n = tid >> 3, f0 = (tid & 7) << 3;
        ull acc[4];
        acc[0] = *(const ull*)(p.b4a + f0);
        acc[1] = *(const ull*)(p.b4a + f0 + 2);
        acc[2] = *(const ull*)(p.b4a + f0 + 4);
        acc[3] = *(const ull*)(p.b4a + f0 + 6);
        #pragma unroll 4
        for (int k = 0; k < 32; ++k) {
            ull aa = dup2(sNT[k*33 + n]);
            ulonglong2 w0 = *(const ulonglong2*)(p.W4a + k*64 + f0);
            ulonglong2 w1 = *(const ulonglong2*)(p.W4a + k*64 + f0 + 4);
            acc[0] = fma2(aa, w0.x, acc[0]); acc[1] = fma2(aa, w0.y, acc[1]);
            acc[2] = fma2(aa, w1.x, acc[2]); acc[3] = fma2(aa, w1.y, acc[3]);
        }
        #pragma unroll
        for (int o = 0; o < 4; ++o) *(ull*)(bufA + n*68 + f0 + 2*o) = acc[o];
    }
    __syncthreads();
    {   // t2 = t1 @ W4b + b4b : [32][36] into sBase
        const int n = tid >> 3, f0 = (tid & 7) << 2;
        ull a01 = *(const ull*)(p.b4b + f0);
        ull a23 = *(const ull*)(p.b4b + f0 + 2);
        const float* r = bufA + n*68;
        #pragma unroll 4
        for (int k = 0; k < 64; ++k) {
            ull aa = dup2(r[k]);
            ulonglong2 w2 = *(const ulonglong2*)(p.W4b + k*32 + f0);
            a01 = fma2(aa, w2.x, a01);
            a23 = fma2(aa, w2.y, a23);
        }
        *(ull*)(sBase + n*36 + f0)     = a01;
        *(ull*)(sBase + n*36 + f0 + 2) = a23;
    }
    __syncthreads();
    {   // t3 = t2 @ W4c + b4c : [32][36] into sProj
        const int n = tid >> 3, f0 = (tid & 7) << 2;
        ull a01 = *(const ull*)(p.b4c + f0);
        ull a23 = *(const ull*)(p.b4c + f0 + 2);
        const float* r = sBase + n*36;
        #pragma unroll 4
        for (int k = 0; k < 32; ++k) {
            ull aa = dup2(r[k]);
            ulonglong2 w2 = *(const ulonglong2*)(p.W4c + k*32 + f0);
            a01 = fma2(aa, w2.x, a01);
            a23 = fma2(aa, w2.y, a23);
        }
        *(ull*)(sProj + n*36 + f0)     = a01;
        *(ull*)(sProj + n*36 + f0 + 2) = a23;
    }
    __syncthreads();
    {   // t4 = t3 @ W5a + b5a : [32][18] into sBase
        const int n = tid >> 3, f0 = (tid & 7) << 1;
        float a0 = p.b5a[f0], a1 = p.b5a[f0 + 1];
        const float* r = sProj + n*36;
        #pragma unroll 8
        for (int k = 0; k < 32; ++k) {
            float a = r[k];
            a0 += a * p.W5a[k*16 + f0];
            a1 += a * p.W5a[k*16 + f0 + 1];
        }
        sBase[n*18 + f0]     = a0;
        sBase[n*18 + f0 + 1] = a1;
    }
    __syncthreads();
    if (tid < 64) {
        const int n = tid >> 1, col = tid & 1;
        float acc = p.b5b[col];
        const float* r = sBase + n*18;
        #pragma unroll
        for (int k = 0; k < 16; ++k) acc += r[k] * p.W5b[k*2 + col];
        if (col == 0) p.out[b*32 + n] = acc;
        else          p.out[32768 + b*32 + n] = 1.0f / acc;
    }
}

extern "C" void kernel_launch(void* const* d_in, const int* in_sizes, int n_in,
                              void* d_out, int out_size) {
    const int has_iter = (n_in >= 32) ? 1 : 0;
    const int base = has_iter ? 8 : 7;

    GnnParams p;
    p.node0 = (const float*)d_in[0];
    p.edge  = (const float*)d_in[1];
    p.h0    = (const float*)d_in[2];
    p.mean  = (const float*)d_in[3];
    p.vari  = (const float*)d_in[4];
    p.iterp = has_iter ? (const int*)d_in[7] : nullptr;
    p.W1a = (const float*)d_in[base+0];  p.b1a = (const float*)d_in[base+1];
    p.W2a = (const float*)d_in[base+2];  p.b2a = (const float*)d_in[base+3];
    p.W2b = (const float*)d_in[base+4];  p.b2b = (const float*)d_in[base+5];
    p.W2c = (const float*)d_in[base+6];  p.b2c = (const float*)d_in[base+7];
    p.Wih = (const float*)d_in[base+8];  p.Whh = (const float*)d_in[base+9];
    p.bih = (const float*)d_in[base+10]; p.bhh = (const float*)d_in[base+11];
    p.W3b = (const float*)d_in[base+12]; p.b3b = (const float*)d_in[base+13];
    p.W4a = (const float*)d_in[base+14]; p.b4a = (const float*)d_in[base+15];
    p.W4b = (const float*)d_in[base+16]; p.b4b = (const float*)d_in[base+17];
    p.W4c = (const float*)d_in[base+18]; p.b4c = (const float*)d_in[base+19];
    p.W5a = (const float*)d_in[base+20]; p.b5a = (const float*)d_in[base+21];
    p.W5b = (const float*)d_in[base+22]; p.b5b = (const float*)d_in[base+23];
    p.out = (float*)d_out;

    cudaFuncSetAttribute(gnn_kernel,
                         cudaFuncAttributeMaxDynamicSharedMemorySize,
                         SMEM_FLOATS * (int)sizeof(float));
    gnn_kernel<<<1024, NT, SMEM_FLOATS * sizeof(float)>>>(p);
}

// round 10
// speedup vs baseline: 1.7276x; 1.0548x over previous
#include <cuda_runtime.h>
#include <math.h>

#define NT 256
typedef unsigned long long ull;

// Shared layout (float offsets)
#define OFF_NT    0        // nodeT [32 feat][32 node] stride 33 = 1056
#define OFF_H     1056     // [32][65] = 2080
#define OFF_MI    3136     // [32][36] = 1152
#define OFF_EDGE  4288     // [992][2] = 1984
#define OFF_BASE  6272     // [32][66] = 2112
#define OFF_PROJ  8384     // [32][66] = 2112
#define OFF_A     10496    // staging W2a[0:64]+b2a (4160) / readout t1 (2176)
#define OFF_W2B2  14656    // W2b: 2048 floats
#define OFF_W2C2  16704    // W2c: 1024 floats
#define OFF_W45S  17728    // W2a rows 64,65: 128 floats
#define OFF_B2B   17856    // 32
#define OFF_B2C   17888    // 32
#define SMEM_FLOATS 17920  // 71,680 B

__device__ __forceinline__ float rcp_fast(float x) {
    float r; asm("rcp.approx.f32 %0, %1;" : "=f"(r) : "f"(x)); return r;
}
// Branch-free GELU: A&S 7.1.26 erf, transcendentals on the MUFU pipe.
// ~12 FMA-class + 2 MUFU; abs err on erf ~5e-7.
__device__ __forceinline__ float gelu_f(float x) {
    float s = x * 0.7071067811865476f;
    float a = fabsf(s);
    float v = fmaf(0.3275911f, a, 1.0f);
    float r = rcp_fast(v);                 // t = 1/(1+p|s|)
    float ex = __expf(-a * a);             // e^{-s^2} (EX2)
    float q = 1.061405429f;
    q = fmaf(q, r, -1.453152027f);
    q = fmaf(q, r, 1.421413741f);
    q = fmaf(q, r, -0.284496736f);
    q = fmaf(q, r, 0.254829592f);
    q = q * r;
    float E = fmaf(-q, ex, 1.0f);          // erf(|s|)
    E = copysignf(E, s);
    return 0.5f * x * (1.0f + E);
}
__device__ __forceinline__ float sigm_f(float x) {
    return rcp_fast(1.0f + __expf(-x));
}
__device__ __forceinline__ ull pack2(float lo, float hi) {
    ull r; asm("mov.b64 %0, {%1, %2};" : "=l"(r) : "f"(lo), "f"(hi)); return r;
}
__device__ __forceinline__ ull dup2(float x) { return pack2(x, x); }
__device__ __forceinline__ void unpack2(ull v, float& lo, float& hi) {
    asm("mov.b64 {%0, %1}, %2;" : "=f"(lo), "=f"(hi) : "l"(v));
}
__device__ __forceinline__ ull fma2(ull a, ull b, ull c) {
    ull d; asm("fma.rn.f32x2 %0, %1, %2, %3;" : "=l"(d) : "l"(a), "l"(b), "l"(c));
    return d;
}
__device__ __forceinline__ ull add2(ull a, ull b) {
    ull d; asm("add.rn.f32x2 %0, %1, %2;" : "=l"(d) : "l"(a), "l"(b));
    return d;
}
__device__ __forceinline__ ull shflxor64(ull v, int m) {
    unsigned lo = (unsigned)v, hi = (unsigned)(v >> 32);
    lo = __shfl_xor_sync(0xffffffffu, lo, m);
    hi = __shfl_xor_sync(0xffffffffu, hi, m);
    return ((ull)hi << 32) | lo;
}

struct GnnParams {
    const float *node0, *edge, *h0, *mean, *vari;
    const int   *iterp;
    const float *W1a, *b1a, *W2a, *b2a, *W2b, *b2b, *W2c, *b2c;
    const float *Wih, *Whh, *bih, *bhh, *W3b, *b3b;
    const float *W4a, *b4a, *W4b, *b4b, *W4c, *b4c, *W5a, *b5a, *W5b, *b5b;
    float *out;
};

__global__ __launch_bounds__(NT, 1)
void gnn_kernel(GnnParams p) {
    extern __shared__ float sm[];
    const int tid  = threadIdx.x;
    const int b    = blockIdx.x;
    const int warp = tid >> 5, lane = tid & 31;

    float* sNT   = sm + OFF_NT;
    float* sH    = sm + OFF_H;     // stride 65
    float* sMi   = sm + OFF_MI;    // stride 36
    float* sEdge = sm + OFF_EDGE;
    float* sBase = sm + OFF_BASE;  // stride 66
    float* sProj = sm + OFF_PROJ;  // stride 66
    float* bufA  = sm + OFF_A;
    const ull* wB   = (const ull*)(sm + OFF_W2B2);
    const ull* wC   = (const ull*)(sm + OFF_W2C2);
    const ull* w45u = (const ull*)(sm + OFF_W45S);
    const ull* bB   = (const ull*)(sm + OFF_B2B);
    const ull* bC   = (const ull*)(sm + OFF_B2C);

    // ---- init copies (once) ----
    for (int i = tid; i < 992*2; i += NT) sEdge[i] = p.edge[b*1984 + i];
    for (int i = tid; i < 32*64; i += NT) {
        int n = i >> 6, k = i & 63;
        sH[n*65 + k] = p.h0[b*2048 + i];
    }
    for (int i = tid; i < 2048;  i += NT) sm[OFF_W2B2 + i] = p.W2b[i];
    for (int i = tid; i < 1024;  i += NT) sm[OFF_W2C2 + i] = p.W2c[i];
    for (int i = tid; i < 128;   i += NT) sm[OFF_W45S + i] = p.W2a[64*64 + i];
    for (int i = tid; i < 32;    i += NT) {
        sm[OFF_B2B + i] = p.b2b[i];
        sm[OFF_B2C + i] = p.b2c[i];
    }
    if (tid < 32) {
        sMi[tid*36 + 32] = p.mean[b*32 + tid];
        sMi[tid*36 + 33] = 1.0f / p.vari[b*32 + tid];
    }
    for (int i = tid; i < 1024; i += NT) sBase[i] = p.node0[b*1024 + i];
    for (int i = tid; i < 4096; i += NT) bufA[i] = p.W2a[i];
    for (int i = tid + 4096; i < 4160; i += NT) bufA[i] = p.b2a[i - 4096];
    __syncthreads();

    // ---- node = node0 @ W1a + b1a (write transposed into sNT) ----
    {
        const int n = tid >> 3, f0 = (tid & 7) << 2;
        float a0 = p.b1a[f0], a1 = p.b1a[f0+1], a2 = p.b1a[f0+2], a3 = p.b1a[f0+3];
        const float* r = sBase + n*32;
        #pragma unroll 8
        for (int k = 0; k < 32; ++k) {
            float a = r[k];
            float4 w = *(const float4*)(p.W1a + k*32 + f0);
            a0 += a*w.x; a1 += a*w.y; a2 += a*w.z; a3 += a*w.w;
        }
        sNT[(f0+0)*33 + n] = a0; sNT[(f0+1)*33 + n] = a1;
        sNT[(f0+2)*33 + n] = a2; sNT[(f0+3)*33 + n] = a3;
    }
    __syncthreads();

    const int iters = p.iterp ? *p.iterp : 3;

    for (int it = 0; it < iters; ++it) {
        // ---- base = node@W2a[0:32]+b2a ; proj = node@W2a[32:64] ----
        {
            const int n = tid >> 3, c0 = (tid & 7) << 3;
            ull bacc[4], pacc[4];
            {
                ulonglong2 b0 = *(const ulonglong2*)(bufA + 4096 + c0);
                ulonglong2 b1 = *(const ulonglong2*)(bufA + 4096 + c0 + 4);
                bacc[0]=b0.x; bacc[1]=b0.y; bacc[2]=b1.x; bacc[3]=b1.y;
            }
            const ull z = dup2(0.0f);
            #pragma unroll
            for (int o = 0; o < 4; ++o) pacc[o] = z;
            #pragma unroll 4
            for (int k = 0; k < 32; ++k) {
                ull aa = dup2(sNT[k*33 + n]);
                ulonglong2 wb0 = *(const ulonglong2*)(bufA + k*64 + c0);
                ulonglong2 wb1 = *(const ulonglong2*)(bufA + k*64 + c0 + 4);
                ulonglong2 wp0 = *(const ulonglong2*)(bufA + (32+k)*64 + c0);
                ulonglong2 wp1 = *(const ulonglong2*)(bufA + (32+k)*64 + c0 + 4);
                bacc[0] = fma2(aa, wb0.x, bacc[0]); bacc[1] = fma2(aa, wb0.y, bacc[1]);
                bacc[2] = fma2(aa, wb1.x, bacc[2]); bacc[3] = fma2(aa, wb1.y, bacc[3]);
                pacc[0] = fma2(aa, wp0.x, pacc[0]); pacc[1] = fma2(aa, wp0.y, pacc[1]);
                pacc[2] = fma2(aa, wp1.x, pacc[2]); pacc[3] = fma2(aa, wp1.y, pacc[3]);
            }
            #pragma unroll
            for (int o = 0; o < 4; ++o) {
                *(ull*)(sBase + n*66 + c0 + 2*o) = bacc[o];
                *(ull*)(sProj + n*66 + c0 + 2*o) = pacc[o];
            }
        }
        __syncthreads();

        // ---- edge phase: warp = node i, lane = edge q; register-resident ----
        for (int pass = 0; pass < 4; ++pass) {
            const int i = pass * 8 + warp;
            const int q = (lane < 31) ? lane : 30;
            const int j = q + (q >= i);
            const ull ev = *(const ull*)(sEdge + (i*31 + q)*2);
            float e0f, e1f; unpack2(ev, e0f, e1f);
            const ull e0d = dup2(e0f), e1d = dup2(e1f);
            const float* prj = sProj + j*66;
            const float* bas = sBase + i*66;

            ull acc[16];
            #pragma unroll
            for (int cp = 0; cp < 16; ++cp) acc[cp] = bB[cp];

            #pragma unroll 4
            for (int t = 0; t < 32; ++t) {
                ull bst = *(const ull*)(bas + 2*t);   // warp-uniform: broadcast
                ull pr2 = *(const ull*)(prj + 2*t);
                ull u = add2(bst, pr2);
                u = fma2(e0d, w45u[t], u);
                u = fma2(e1d, w45u[32 + t], u);
                float g0, g1; unpack2(u, g0, g1);
                ull a0 = dup2(gelu_f(g0)), a1 = dup2(gelu_f(g1));
                #pragma unroll
                for (int cp2 = 0; cp2 < 8; ++cp2) {
                    ulonglong2 w0 = *(const ulonglong2*)(wB + (2*t)*16 + 2*cp2);
                    ulonglong2 w1 = *(const ulonglong2*)(wB + (2*t+1)*16 + 2*cp2);
                    acc[2*cp2]   = fma2(a0, w0.x, acc[2*cp2]);
                    acc[2*cp2+1] = fma2(a0, w0.y, acc[2*cp2+1]);
                    acc[2*cp2]   = fma2(a1, w1.x, acc[2*cp2]);
                    acc[2*cp2+1] = fma2(a1, w1.y, acc[2*cp2+1]);
                }
            }

            // layer 3 from registers
            ull macc[16];
            #pragma unroll
            for (int cp = 0; cp < 16; ++cp) macc[cp] = bC[cp];
            #pragma unroll 4
            for (int cqp = 0; cqp < 16; ++cqp) {
                float v0, v1; unpack2(acc[cqp], v0, v1);
                ull a0 = dup2(gelu_f(v0)), a1 = dup2(gelu_f(v1));
                #pragma unroll
                for (int cp2 = 0; cp2 < 8; ++cp2) {
                    ulonglong2 w0 = *(const ulonglong2*)(wC + (2*cqp)*16 + 2*cp2);
                    ulonglong2 w1 = *(const ulonglong2*)(wC + (2*cqp+1)*16 + 2*cp2);
                    macc[2*cp2]   = fma2(a0, w0.x, macc[2*cp2]);
                    macc[2*cp2+1] = fma2(a0, w0.y, macc[2*cp2+1]);
                    macc[2*cp2]   = fma2(a1, w1.x, macc[2*cp2]);
                    macc[2*cp2+1] = fma2(a1, w1.y, macc[2*cp2+1]);
                }
            }

            // gelu + mask dummy lane
            #pragma unroll
            for (int cp = 0; cp < 16; ++cp) {
                float v0, v1; unpack2(macc[cp], v0, v1);
                macc[cp] = (lane < 31) ? pack2(gelu_f(v0), gelu_f(v1)) : 0ULL;
            }
            // Butterfly transpose-reduce: lane ends with the full edge-sum of
            // element bitrev4(lane&15) in macc[0] (static register index).
            #pragma unroll
            for (int s = 0; s < 4; ++s) {
                const int off = 1 << s;
                const int h = 8 >> s;
                const bool keep_low = ((lane >> s) & 1) == 0;
                #pragma unroll
                for (int r = 0; r < 8; ++r) {
                    if (r < h) {
                        ull send = keep_low ? macc[r + h] : macc[r];
                        ull recv = shflxor64(send, off);
                        ull mine = keep_low ? macc[r] : macc[r + h];
                        macc[r] = add2(mine, recv);
                    }
                }
            }
            macc[0] = add2(macc[0], shflxor64(macc[0], 16));
            if (lane < 16) {
                const int e = ((lane & 1) << 3) | (((lane >> 1) & 1) << 2) |
                              (((lane >> 2) & 1) << 1) | ((lane >> 3) & 1);
                *(ull*)(sMi + i*36 + 2*e) = macc[0];
            }
        }
        __syncthreads();

        // ---- GRU cell (GELU new gate), packed col-pairs ----
        {
            const int n  = tid >> 3;
            const int c0 = (tid & 7) << 3;
            ull ar[4], az[4], an_[4], hn_[4];
            #pragma unroll
            for (int o = 0; o < 4; ++o) {
                ull bi_r = *(const ull*)(p.bih + c0 + 2*o);
                ull bh_r = *(const ull*)(p.bhh + c0 + 2*o);
                ull bi_z = *(const ull*)(p.bih + 64 + c0 + 2*o);
                ull bh_z = *(const ull*)(p.bhh + 64 + c0 + 2*o);
                ar[o]  = add2(bi_r, bh_r);
                az[o]  = add2(bi_z, bh_z);
                an_[o] = *(const ull*)(p.bih + 128 + c0 + 2*o);
                hn_[o] = *(const ull*)(p.bhh + 128 + c0 + 2*o);
            }
            const float* mi = sMi + n*36;
            #pragma unroll 2
            for (int k = 0; k < 34; ++k) {
                ull aa = dup2(mi[k]);
                const float* w = p.Wih + k*192;
                ulonglong2 r01 = *(const ulonglong2*)(w + c0);
                ulonglong2 r23 = *(const ulonglong2*)(w + c0 + 4);
                ulonglong2 z01 = *(const ulonglong2*)(w + 64 + c0);
                ulonglong2 z23 = *(const ulonglong2*)(w + 64 + c0 + 4);
                ulonglong2 n01 = *(const ulonglong2*)(w + 128 + c0);
                ulonglong2 n23 = *(const ulonglong2*)(w + 128 + c0 + 4);
                ar[0]=fma2(aa,r01.x,ar[0]); ar[1]=fma2(aa,r01.y,ar[1]);
                ar[2]=fma2(aa,r23.x,ar[2]); ar[3]=fma2(aa,r23.y,ar[3]);
                az[0]=fma2(aa,z01.x,az[0]); az[1]=fma2(aa,z01.y,az[1]);
                az[2]=fma2(aa,z23.x,az[2]); az[3]=fma2(aa,z23.y,az[3]);
                an_[0]=fma2(aa,n01.x,an_[0]); an_[1]=fma2(aa,n01.y,an_[1]);
                an_[2]=fma2(aa,n23.x,an_[2]); an_[3]=fma2(aa,n23.y,an_[3]);
            }
            const float* hv = sH + n*65;
            #pragma unroll 2
            for (int k = 0; k < 64; ++k) {
                ull aa = dup2(hv[k]);
                const float* w = p.Whh + k*192;
                ulonglong2 r01 = *(const ulonglong2*)(w + c0);
                ulonglong2 r23 = *(const ulonglong2*)(w + c0 + 4);
                ulonglong2 z01 = *(const ulonglong2*)(w + 64 + c0);
                ulonglong2 z23 = *(const ulonglong2*)(w + 64 + c0 + 4);
                ulonglong2 n01 = *(const ulonglong2*)(w + 128 + c0);
                ulonglong2 n23 = *(const ulonglong2*)(w + 128 + c0 + 4);
                ar[0]=fma2(aa,r01.x,ar[0]); ar[1]=fma2(aa,r01.y,ar[1]);
                ar[2]=fma2(aa,r23.x,ar[2]); ar[3]=fma2(aa,r23.y,ar[3]);
                az[0]=fma2(aa,z01.x,az[0]); az[1]=fma2(aa,z01.y,az[1]);
                az[2]=fma2(aa,z23.x,az[2]); az[3]=fma2(aa,z23.y,az[3]);
                hn_[0]=fma2(aa,n01.x,hn_[0]); hn_[1]=fma2(aa,n01.y,hn_[1]);
                hn_[2]=fma2(aa,n23.x,hn_[2]); hn_[3]=fma2(aa,n23.y,hn_[3]);
            }
            float hnew[8];
            #pragma unroll
            for (int o = 0; o < 4; ++o) {
                float r0, r1, z0, z1, in0, in1, hn0, hn1;
                unpack2(ar[o], r0, r1);
                unpack2(az[o], z0, z1);
                unpack2(an_[o], in0, in1);
                unpack2(hn_[o], hn0, hn1);
                float rr0 = sigm_f(r0), rr1 = sigm_f(r1);
                float zz0 = sigm_f(z0), zz1 = sigm_f(z1);
                float g0 = gelu_f(in0 + rr0 * hn0);
                float g1 = gelu_f(in1 + rr1 * hn1);
                hnew[2*o]   = (1.0f - zz0) * g0 + zz0 * hv[c0 + 2*o];
                hnew[2*o+1] = (1.0f - zz1) * g1 + zz1 * hv[c0 + 2*o + 1];
            }
            __syncthreads();
            #pragma unroll
            for (int o = 0; o < 8; ++o) sH[n*65 + c0 + o] = hnew[o];
        }
        __syncthreads();

        // ---- node = h @ W3b + b3b  (packed, write transposed into sNT) ----
        {
            const int n = tid >> 3, f0 = (tid & 7) << 2;
            ull a01 = *(const ull*)(p.b3b + f0);
            ull a23 = *(const ull*)(p.b3b + f0 + 2);
            const float* hv = sH + n*65;
            #pragma unroll 4
            for (int k = 0; k < 64; ++k) {
                ull aa = dup2(hv[k]);
                ulonglong2 w2 = *(const ulonglong2*)(p.W3b + k*32 + f0);
                a01 = fma2(aa, w2.x, a01);
                a23 = fma2(aa, w2.y, a23);
            }
            float v0, v1, v2, v3;
            unpack2(a01, v0, v1); unpack2(a23, v2, v3);
            sNT[(f0+0)*33 + n] = v0; sNT[(f0+1)*33 + n] = v1;
            sNT[(f0+2)*33 + n] = v2; sNT[(f0+3)*33 + n] = v3;
        }
        __syncthreads();
    }

    // ---- readout (scratch: bufA=t1, sBase=t2, sProj=t3, sBase=t4) ----
    {   // t1 = node @ W4a + b4a : [32][68]
        const int n = tid >> 3, f0 = (tid & 7) << 3;
        ull acc[4];
        acc[0] = *(const ull*)(p.b4a + f0);
        acc[1] = *(const ull*)(p.b4a + f0 + 2);
        acc[2] = *(const ull*)(p.b4a + f0 + 4);
        acc[3] = *(const ull*)(p.b4a + f0 + 6);
        #pragma unroll 4
        for (int k = 0; k < 32; ++k) {
            ull aa = dup2(sNT[k*33 + n]);
            ulonglong2 w0 = *(const ulonglong2*)(p.W4a + k*64 + f0);
            ulonglong2 w1 = *(const ulonglong2*)(p.W4a + k*64 + f0 + 4);
            acc[0] = fma2(aa, w0.x, acc[0]); acc[1] = fma2(aa, w0.y, acc[1]);
            acc[2] = fma2(aa, w1.x, acc[2]); acc[3] = fma2(aa, w1.y, acc[3]);
        }
        #pragma unroll
        for (int o = 0; o < 4; ++o) *(ull*)(bufA + n*68 + f0 + 2*o) = acc[o];
    }
    __syncthreads();
    {   // t2 = t1 @ W4b + b4b : [32][36] into sBase
        const int n = tid >> 3, f0 = (tid & 7) << 2;
        ull a01 = *(const ull*)(p.b4b + f0);
        ull a23 = *(const ull*)(p.b4b + f0 + 2);
        const float* r = bufA + n*68;
        #pragma unroll 4
        for (int k = 0; k < 64; ++k) {
            ull aa = dup2(r[k]);
            ulonglong2 w2 = *(const ulonglong2*)(p.W4b + k*32 + f0);
            a01 = fma2(aa, w2.x, a01);
            a23 = fma2(aa, w2.y, a23);
        }
        *(ull*)(sBase + n*36 + f0)     = a01;
        *(ull*)(sBase + n*36 + f0 + 2) = a23;
    }
    __syncthreads();
    {   // t3 = t2 @ W4c + b4c : [32][36] into sProj
        const int n = tid >> 3, f0 = (tid & 7) << 2;
        ull a01 = *(const ull*)(p.b4c + f0);
        ull a23 = *(const ull*)(p.b4c + f0 + 2);
        const float* r = sBase + n*36;
        #pragma unroll 4
        for (int k = 0; k < 32; ++k) {
            ull aa = dup2(r[k]);
            ulonglong2 w2 = *(const ulonglong2*)(p.W4c + k*32 + f0);
            a01 = fma2(aa, w2.x, a01);
            a23 = fma2(aa, w2.y, a23);
        }
        *(ull*)(sProj + n*36 + f0)     = a01;
        *(ull*)(sProj + n*36 + f0 + 2) = a23;
    }
    __syncthreads();
    {   // t4 = t3 @ W5a + b5a : [32][18] into sBase
        const int n = tid >> 3, f0 = (tid & 7) << 1;
        float a0 = p.b5a[f0], a1 = p.b5a[f0 + 1];
        const float* r = sProj + n*36;
        #pragma unroll 8
        for (int k = 0; k < 32; ++k) {
            float a = r[k];
            a0 += a * p.W5a[k*16 + f0];
            a1 += a * p.W5a[k*16 + f0 + 1];
        }
        sBase[n*18 + f0]     = a0;
        sBase[n*18 + f0 + 1] = a1;
    }
    __syncthreads();
    if (tid < 64) {
        const int n = tid >> 1, col = tid & 1;
        float acc = p.b5b[col];
        const float* r = sBase + n*18;
        #pragma unroll
        for (int k = 0; k < 16; ++k) acc += r[k] * p.W5b[k*2 + col];
        if (col == 0) p.out[b*32 + n] = acc;
        else          p.out[32768 + b*32 + n] = 1.0f / acc;
    }
}

extern "C" void kernel_launch(void* const* d_in, const int* in_sizes, int n_in,
                              void* d_out, int out_size) {
    const int has_iter = (n_in >= 32) ? 1 : 0;
    const int base = has_iter ? 8 : 7;

    GnnParams p;
    p.node0 = (const float*)d_in[0];
    p.edge  = (const float*)d_in[1];
    p.h0    = (const float*)d_in[2];
    p.mean  = (const float*)d_in[3];
    p.vari  = (const float*)d_in[4];
    p.iterp = has_iter ? (const int*)d_in[7] : nullptr;
    p.W1a = (const float*)d_in[base+0];  p.b1a = (const float*)d_in[base+1];
    p.W2a = (const float*)d_in[base+2];  p.b2a = (const float*)d_in[base+3];
    p.W2b = (const float*)d_in[base+4];  p.b2b = (const float*)d_in[base+5];
    p.W2c = (const float*)d_in[base+6];  p.b2c = (const float*)d_in[base+7];
    p.Wih = (const float*)d_in[base+8];  p.Whh = (const float*)d_in[base+9];
    p.bih = (const float*)d_in[base+10]; p.bhh = (const float*)d_in[base+11];
    p.W3b = (const float*)d_in[base+12]; p.b3b = (const float*)d_in[base+13];
    p.W4a = (const float*)d_in[base+14]; p.b4a = (const float*)d_in[base+15];
    p.W4b = (const float*)d_in[base+16]; p.b4b = (const float*)d_in[base+17];
    p.W4c = (const float*)d_in[base+18]; p.b4c = (const float*)d_in[base+19];
    p.W5a = (const float*)d_in[base+20]; p.b5a = (const float*)d_in[base+21];
    p.W5b = (const float*)d_in[base+22]; p.b5b = (const float*)d_in[base+23];
    p.out = (float*)d_out;

    cudaFuncSetAttribute(gnn_kernel,
                         cudaFuncAttributeMaxDynamicSharedMemorySize,
                         SMEM_FLOATS * (int)sizeof(float));
    gnn_kernel<<<1024, NT, SMEM_FLOATS * sizeof(float)>>>(p);
}

// round 11
// speedup vs baseline: 1.9729x; 1.1420x over previous
#include <cuda_runtime.h>
#include <math.h>

#define NT 256
typedef unsigned long long ull;

// Shared layout (float offsets)
#define OFF_NT    0        // nodeT [32 feat][32 node] stride 33 = 1056
#define OFF_H     1056     // [32][65] = 2080
#define OFF_MI    3136     // [32][36] = 1152
#define OFF_EDGE  4288     // [992][2] = 1984
#define OFF_BASE  6272     // [32][66] = 2112
#define OFF_PROJ  8384     // [32][66] = 2112
#define OFF_A     10496    // staging W2a[0:64]+b2a (4160) / readout t1 (2176)
#define OFF_W2B2  14656    // W2b: 2048 floats
#define OFF_W2C2  16704    // wCt paired-transposed W2c: 512 ull = 1024 floats
#define OFF_W45S  17728    // W2a rows 64,65: 128 floats
#define OFF_B2B   17856    // 32
#define OFF_B2C   17888    // 32
#define SMEM_FLOATS 17920  // 71,680 B -> 2 CTAs/SM

__device__ __forceinline__ float rcp_fast(float x) {
    float r; asm("rcp.approx.f32 %0, %1;" : "=f"(r) : "f"(x)); return r;
}
// Branch-free GELU: A&S 7.1.26 erf, transcendentals on the MUFU pipe.
__device__ __forceinline__ float gelu_f(float x) {
    float s = x * 0.7071067811865476f;
    float a = fabsf(s);
    float v = fmaf(0.3275911f, a, 1.0f);
    float r = rcp_fast(v);                 // t = 1/(1+p|s|)
    float ex = __expf(-a * a);             // e^{-s^2} (EX2)
    float q = 1.061405429f;
    q = fmaf(q, r, -1.453152027f);
    q = fmaf(q, r, 1.421413741f);
    q = fmaf(q, r, -0.284496736f);
    q = fmaf(q, r, 0.254829592f);
    q = q * r;
    float E = fmaf(-q, ex, 1.0f);          // erf(|s|)
    E = copysignf(E, s);
    return 0.5f * x * (1.0f + E);
}
__device__ __forceinline__ float sigm_f(float x) {
    return rcp_fast(1.0f + __expf(-x));
}
__device__ __forceinline__ ull pack2(float lo, float hi) {
    ull r; asm("mov.b64 %0, {%1, %2};" : "=l"(r) : "f"(lo), "f"(hi)); return r;
}
__device__ __forceinline__ ull dup2(float x) { return pack2(x, x); }
__device__ __forceinline__ void unpack2(ull v, float& lo, float& hi) {
    asm("mov.b64 {%0, %1}, %2;" : "=f"(lo), "=f"(hi) : "l"(v));
}
__device__ __forceinline__ ull fma2(ull a, ull b, ull c) {
    ull d; asm("fma.rn.f32x2 %0, %1, %2, %3;" : "=l"(d) : "l"(a), "l"(b), "l"(c));
    return d;
}
__device__ __forceinline__ ull add2(ull a, ull b) {
    ull d; asm("add.rn.f32x2 %0, %1, %2;" : "=l"(d) : "l"(a), "l"(b));
    return d;
}

struct GnnParams {
    const float *node0, *edge, *h0, *mean, *vari;
    const int   *iterp;
    const float *W1a, *b1a, *W2a, *b2a, *W2b, *b2b, *W2c, *b2c;
    const float *Wih, *Whh, *bih, *bhh, *W3b, *b3b;
    const float *W4a, *b4a, *W4b, *b4b, *W4c, *b4c, *W5a, *b5a, *W5b, *b5b;
    float *out;
};

__global__ __launch_bounds__(NT, 2)
void gnn_kernel(GnnParams p) {
    extern __shared__ float sm[];
    const int tid  = threadIdx.x;
    const int b    = blockIdx.x;
    const int warp = tid >> 5, lane = tid & 31;

    float* sNT   = sm + OFF_NT;
    float* sH    = sm + OFF_H;     // stride 65
    float* sMi   = sm + OFF_MI;    // stride 36
    float* sEdge = sm + OFF_EDGE;
    float* sBase = sm + OFF_BASE;  // stride 66
    float* sProj = sm + OFF_PROJ;  // stride 66
    float* bufA  = sm + OFF_A;
    const ull*   wB   = (const ull*)(sm + OFF_W2B2);
    const ull*   wCt  = (const ull*)(sm + OFF_W2C2);   // [c][qp] paired-k
    const ull*   w45u = (const ull*)(sm + OFF_W45S);
    const ull*   bB   = (const ull*)(sm + OFF_B2B);
    const float* bCs  = sm + OFF_B2C;

    // ---- init copies (once) ----
    for (int i = tid; i < 992*2; i += NT) sEdge[i] = p.edge[b*1984 + i];
    for (int i = tid; i < 32*64; i += NT) {
        int n = i >> 6, k = i & 63;
        sH[n*65 + k] = p.h0[b*2048 + i];
    }
    for (int i = tid; i < 2048;  i += NT) sm[OFF_W2B2 + i] = p.W2b[i];
    for (int i = tid; i < 512;   i += NT) {       // wCt[c*16+qp] = (W2c[2qp][c], W2c[2qp+1][c])
        int c = i >> 4, qp = i & 15;
        ((ull*)(sm + OFF_W2C2))[i] =
            pack2(p.W2c[(2*qp)*32 + c], p.W2c[(2*qp+1)*32 + c]);
    }
    for (int i = tid; i < 128;   i += NT) sm[OFF_W45S + i] = p.W2a[64*64 + i];
    for (int i = tid; i < 32;    i += NT) {
        sm[OFF_B2B + i] = p.b2b[i];
        sm[OFF_B2C + i] = p.b2c[i];
    }
    if (tid < 32) {
        sMi[tid*36 + 32] = p.mean[b*32 + tid];
        sMi[tid*36 + 33] = 1.0f / p.vari[b*32 + tid];
    }
    for (int i = tid; i < 1024; i += NT) sBase[i] = p.node0[b*1024 + i];
    for (int i = tid; i < 4096; i += NT) bufA[i] = p.W2a[i];
    for (int i = tid + 4096; i < 4160; i += NT) bufA[i] = p.b2a[i - 4096];
    __syncthreads();

    // ---- node = node0 @ W1a + b1a (write transposed into sNT) ----
    {
        const int n = tid >> 3, f0 = (tid & 7) << 2;
        float a0 = p.b1a[f0], a1 = p.b1a[f0+1], a2 = p.b1a[f0+2], a3 = p.b1a[f0+3];
        const float* r = sBase + n*32;
        #pragma unroll 8
        for (int k = 0; k < 32; ++k) {
            float a = r[k];
            float4 w = *(const float4*)(p.W1a + k*32 + f0);
            a0 += a*w.x; a1 += a*w.y; a2 += a*w.z; a3 += a*w.w;
        }
        sNT[(f0+0)*33 + n] = a0; sNT[(f0+1)*33 + n] = a1;
        sNT[(f0+2)*33 + n] = a2; sNT[(f0+3)*33 + n] = a3;
    }
    __syncthreads();

    const int iters = p.iterp ? *p.iterp : 3;

    for (int it = 0; it < iters; ++it) {
        // ---- base = node@W2a[0:32]+b2a ; proj = node@W2a[32:64] ----
        {
            const int n = tid >> 3, c0 = (tid & 7) << 3;
            ull bacc[4], pacc[4];
            {
                ulonglong2 b0 = *(const ulonglong2*)(bufA + 4096 + c0);
                ulonglong2 b1 = *(const ulonglong2*)(bufA + 4096 + c0 + 4);
                bacc[0]=b0.x; bacc[1]=b0.y; bacc[2]=b1.x; bacc[3]=b1.y;
            }
            const ull z = dup2(0.0f);
            #pragma unroll
            for (int o = 0; o < 4; ++o) pacc[o] = z;
            #pragma unroll 4
            for (int k = 0; k < 32; ++k) {
                ull aa = dup2(sNT[k*33 + n]);
                ulonglong2 wb0 = *(const ulonglong2*)(bufA + k*64 + c0);
                ulonglong2 wb1 = *(const ulonglong2*)(bufA + k*64 + c0 + 4);
                ulonglong2 wp0 = *(const ulonglong2*)(bufA + (32+k)*64 + c0);
                ulonglong2 wp1 = *(const ulonglong2*)(bufA + (32+k)*64 + c0 + 4);
                bacc[0] = fma2(aa, wb0.x, bacc[0]); bacc[1] = fma2(aa, wb0.y, bacc[1]);
                bacc[2] = fma2(aa, wb1.x, bacc[2]); bacc[3] = fma2(aa, wb1.y, bacc[3]);
                pacc[0] = fma2(aa, wp0.x, pacc[0]); pacc[1] = fma2(aa, wp0.y, pacc[1]);
                pacc[2] = fma2(aa, wp1.x, pacc[2]); pacc[3] = fma2(aa, wp1.y, pacc[3]);
            }
            #pragma unroll
            for (int o = 0; o < 4; ++o) {
                *(ull*)(sBase + n*66 + c0 + 2*o) = bacc[o];
                *(ull*)(sProj + n*66 + c0 + 2*o) = pacc[o];
            }
        }
        __syncthreads();

        // ---- edge phase: warp = node i, lane = edge q; register-resident ----
        for (int pass = 0; pass < 4; ++pass) {
            const int i = pass * 8 + warp;
            const int q = (lane < 31) ? lane : 30;
            const int j = q + (q >= i);
            const ull ev = *(const ull*)(sEdge + (i*31 + q)*2);
            float e0f, e1f; unpack2(ev, e0f, e1f);
            const ull e0d = dup2(e0f), e1d = dup2(e1f);
            const float* prj = sProj + j*66;
            const float* bas = sBase + i*66;

            ull acc[16];
            #pragma unroll
            for (int cp = 0; cp < 16; ++cp) acc[cp] = bB[cp];

            #pragma unroll 4
            for (int t = 0; t < 32; ++t) {
                ull bst = *(const ull*)(bas + 2*t);   // warp-uniform: broadcast
                ull pr2 = *(const ull*)(prj + 2*t);
                ull u = add2(bst, pr2);
                u = fma2(e0d, w45u[t], u);
                u = fma2(e1d, w45u[32 + t], u);
                float g0, g1; unpack2(u, g0, g1);
                ull a0 = dup2(gelu_f(g0)), a1 = dup2(gelu_f(g1));
                #pragma unroll
                for (int cp2 = 0; cp2 < 8; ++cp2) {
                    ulonglong2 w0 = *(const ulonglong2*)(wB + (2*t)*16 + 2*cp2);
                    ulonglong2 w1 = *(const ulonglong2*)(wB + (2*t+1)*16 + 2*cp2);
                    acc[2*cp2]   = fma2(a0, w0.x, acc[2*cp2]);
                    acc[2*cp2+1] = fma2(a0, w0.y, acc[2*cp2+1]);
                    acc[2*cp2]   = fma2(a1, w1.x, acc[2*cp2]);
                    acc[2*cp2+1] = fma2(a1, w1.y, acc[2*cp2+1]);
                }
            }

            // gelu m2 in place: acc[cp] = (m2_{2cp}, m2_{2cp+1}) = a k-pair
            #pragma unroll
            for (int cp = 0; cp < 16; ++cp) {
                float v0, v1; unpack2(acc[cp], v0, v1);
                acc[cp] = pack2(gelu_f(v0), gelu_f(v1));
            }

            // layer 3: col-at-a-time, paired-k fma2 + horizontal add (no macc bank)
            const float maskv = (lane < 31) ? 1.0f : 0.0f;
            float m3[32];
            #pragma unroll
            for (int c = 0; c < 32; ++c) {
                ull a0 = pack2(bCs[c], 0.0f);
                ull a1 = dup2(0.0f);
                const ull* wr = wCt + c*16;
                #pragma unroll
                for (int jj = 0; jj < 8; ++jj) {
                    ulonglong2 w = *(const ulonglong2*)(wr + 2*jj);
                    a0 = fma2(acc[2*jj],   w.x, a0);
                    a1 = fma2(acc[2*jj+1], w.y, a1);
                }
                a0 = add2(a0, a1);
                float lo, hi; unpack2(a0, lo, hi);
                m3[c] = maskv * gelu_f(lo + hi);
            }

            // scalar butterfly transpose-reduce over 32 cols (31 shfl)
            #pragma unroll
            for (int s = 0; s < 5; ++s) {
                const int off = 1 << s;
                const int h = 16 >> s;
                const bool keep_low = ((lane >> s) & 1) == 0;
                #pragma unroll
                for (int r = 0; r < 16; ++r) {
                    if (r < h) {
                        float send = keep_low ? m3[r + h] : m3[r];
                        float recv = __shfl_xor_sync(0xffffffffu, send, off);
                        float mine = keep_low ? m3[r] : m3[r + h];
                        m3[r] = mine + recv;
                    }
                }
            }
            {
                const int e = ((lane & 1) << 4) | (((lane >> 1) & 1) << 3) |
                              (((lane >> 2) & 1) << 2) | (((lane >> 3) & 1) << 1) |
                              ((lane >> 4) & 1);
                sMi[i*36 + e] = m3[0];
            }
        }
        __syncthreads();

        // ---- GRU cell (GELU new gate), packed col-pairs ----
        {
            const int n  = tid >> 3;
            const int c0 = (tid & 7) << 3;
            ull ar[4], az[4], an_[4], hn_[4];
            #pragma unroll
            for (int o = 0; o < 4; ++o) {
                ull bi_r = *(const ull*)(p.bih + c0 + 2*o);
                ull bh_r = *(const ull*)(p.bhh + c0 + 2*o);
                ull bi_z = *(const ull*)(p.bih + 64 + c0 + 2*o);
                ull bh_z = *(const ull*)(p.bhh + 64 + c0 + 2*o);
                ar[o]  = add2(bi_r, bh_r);
                az[o]  = add2(bi_z, bh_z);
                an_[o] = *(const ull*)(p.bih + 128 + c0 + 2*o);
                hn_[o] = *(const ull*)(p.bhh + 128 + c0 + 2*o);
            }
            const float* mi = sMi + n*36;
            #pragma unroll 2
            for (int k = 0; k < 34; ++k) {
                ull aa = dup2(mi[k]);
                const float* w = p.Wih + k*192;
                ulonglong2 r01 = *(const ulonglong2*)(w + c0);
                ulonglong2 r23 = *(const ulonglong2*)(w + c0 + 4);
                ulonglong2 z01 = *(const ulonglong2*)(w + 64 + c0);
                ulonglong2 z23 = *(const ulonglong2*)(w + 64 + c0 + 4);
                ulonglong2 n01 = *(const ulonglong2*)(w + 128 + c0);
                ulonglong2 n23 = *(const ulonglong2*)(w + 128 + c0 + 4);
                ar[0]=fma2(aa,r01.x,ar[0]); ar[1]=fma2(aa,r01.y,ar[1]);
                ar[2]=fma2(aa,r23.x,ar[2]); ar[3]=fma2(aa,r23.y,ar[3]);
                az[0]=fma2(aa,z01.x,az[0]); az[1]=fma2(aa,z01.y,az[1]);
                az[2]=fma2(aa,z23.x,az[2]); az[3]=fma2(aa,z23.y,az[3]);
                an_[0]=fma2(aa,n01.x,an_[0]); an_[1]=fma2(aa,n01.y,an_[1]);
                an_[2]=fma2(aa,n23.x,an_[2]); an_[3]=fma2(aa,n23.y,an_[3]);
            }
            const float* hv = sH + n*65;
            #pragma unroll 2
            for (int k = 0; k < 64; ++k) {
                ull aa = dup2(hv[k]);
                const float* w = p.Whh + k*192;
                ulonglong2 r01 = *(const ulonglong2*)(w + c0);
                ulonglong2 r23 = *(const ulonglong2*)(w + c0 + 4);
                ulonglong2 z01 = *(const ulonglong2*)(w + 64 + c0);
                ulonglong2 z23 = *(const ulonglong2*)(w + 64 + c0 + 4);
                ulonglong2 n01 = *(const ulonglong2*)(w + 128 + c0);
                ulonglong2 n23 = *(const ulonglong2*)(w + 128 + c0 + 4);
                ar[0]=fma2(aa,r01.x,ar[0]); ar[1]=fma2(aa,r01.y,ar[1]);
                ar[2]=fma2(aa,r23.x,ar[2]); ar[3]=fma2(aa,r23.y,ar[3]);
                az[0]=fma2(aa,z01.x,az[0]); az[1]=fma2(aa,z01.y,az[1]);
                az[2]=fma2(aa,z23.x,az[2]); az[3]=fma2(aa,z23.y,az[3]);
                hn_[0]=fma2(aa,n01.x,hn_[0]); hn_[1]=fma2(aa,n01.y,hn_[1]);
                hn_[2]=fma2(aa,n23.x,hn_[2]); hn_[3]=fma2(aa,n23.y,hn_[3]);
            }
            float hnew[8];
            #pragma unroll
            for (int o = 0; o < 4; ++o) {
                float r0, r1, z0, z1, in0, in1, hn0, hn1;
                unpack2(ar[o], r0, r1);
                unpack2(az[o], z0, z1);
                unpack2(an_[o], in0, in1);
                unpack2(hn_[o], hn0, hn1);
                float rr0 = sigm_f(r0), rr1 = sigm_f(r1);
                float zz0 = sigm_f(z0), zz1 = sigm_f(z1);
                float g0 = gelu_f(in0 + rr0 * hn0);
                float g1 = gelu_f(in1 + rr1 * hn1);
                hnew[2*o]   = (1.0f - zz0) * g0 + zz0 * hv[c0 + 2*o];
                hnew[2*o+1] = (1.0f - zz1) * g1 + zz1 * hv[c0 + 2*o + 1];
            }
            __syncthreads();
            #pragma unroll
            for (int o = 0; o < 8; ++o) sH[n*65 + c0 + o] = hnew[o];
        }
        __syncthreads();

        // ---- node = h @ W3b + b3b  (packed, write transposed into sNT) ----
        {
            const int n = tid >> 3, f0 = (tid & 7) << 2;
            ull a01 = *(const ull*)(p.b3b + f0);
            ull a23 = *(const ull*)(p.b3b + f0 + 2);
            const float* hv = sH + n*65;
            #pragma unroll 4
            for (int k = 0; k < 64; ++k) {
                ull aa = dup2(hv[k]);
                ulonglong2 w2 = *(const ulonglong2*)(p.W3b + k*32 + f0);
                a01 = fma2(aa, w2.x, a01);
                a23 = fma2(aa, w2.y, a23);
            }
            float v0, v1, v2, v3;
            unpack2(a01, v0, v1); unpack2(a23, v2, v3);
            sNT[(f0+0)*33 + n] = v0; sNT[(f0+1)*33 + n] = v1;
            sNT[(f0+2)*33 + n] = v2; sNT[(f0+3)*33 + n] = v3;
        }
        __syncthreads();
    }

    // ---- readout (scratch: bufA=t1, sBase=t2, sProj=t3, sBase=t4) ----
    {   // t1 = node @ W4a + b4a : [32][68]
        const int n = tid >> 3, f0 = (tid & 7) << 3;
        ull acc[4];
        acc[0] = *(const ull*)(p.b4a + f0);
        acc[1] = *(const ull*)(p.b4a + f0 + 2);
        acc[2] = *(const ull*)(p.b4a + f0 + 4);
        acc[3] = *(const ull*)(p.b4a + f0 + 6);
        #pragma unroll 4
        for (int k = 0; k < 32; ++k) {
            ull aa = dup2(sNT[k*33 + n]);
            ulonglong2 w0 = *(const ulonglong2*)(p.W4a + k*64 + f0);
            ulonglong2 w1 = *(const ulonglong2*)(p.W4a + k*64 + f0 + 4);
            acc[0] = fma2(aa, w0.x, acc[0]); acc[1] = fma2(aa, w0.y, acc[1]);
            acc[2] = fma2(aa, w1.x, acc[2]); acc[3] = fma2(aa, w1.y, acc[3]);
        }
        #pragma unroll
        for (int o = 0; o < 4; ++o) *(ull*)(bufA + n*68 + f0 + 2*o) = acc[o];
    }
    __syncthreads();
    {   // t2 = t1 @ W4b + b4b : [32][36] into sBase
        const int n = tid >> 3, f0 = (tid & 7) << 2;
        ull a01 = *(const ull*)(p.b4b + f0);
        ull a23 = *(const ull*)(p.b4b + f0 + 2);
        const float* r = bufA + n*68;
        #pragma unroll 4
        for (int k = 0; k < 64; ++k) {
            ull aa = dup2(r[k]);
            ulonglong2 w2 = *(const ulonglong2*)(p.W4b + k*32 + f0);
            a01 = fma2(aa, w2.x, a01);
            a23 = fma2(aa, w2.y, a23);
        }
        *(ull*)(sBase + n*36 + f0)     = a01;
        *(ull*)(sBase + n*36 + f0 + 2) = a23;
    }
    __syncthreads();
    {   // t3 = t2 @ W4c + b4c : [32][36] into sProj
        const int n = tid >> 3, f0 = (tid & 7) << 2;
        ull a01 = *(const ull*)(p.b4c + f0);
        ull a23 = *(const ull*)(p.b4c + f0 + 2);
        const float* r = sBase + n*36;
        #pragma unroll 4
        for (int k = 0; k < 32; ++k) {
            ull aa = dup2(r[k]);
            ulonglong2 w2 = *(const ulonglong2*)(p.W4c + k*32 + f0);
            a01 = fma2(aa, w2.x, a01);
            a23 = fma2(aa, w2.y, a23);
        }
        *(ull*)(sProj + n*36 + f0)     = a01;
        *(ull*)(sProj + n*36 + f0 + 2) = a23;
    }
    __syncthreads();
    {   // t4 = t3 @ W5a + b5a : [32][18] into sBase
        const int n = tid >> 3, f0 = (tid & 7) << 1;
        float a0 = p.b5a[f0], a1 = p.b5a[f0 + 1];
        const float* r = sProj + n*36;
        #pragma unroll 8
        for (int k = 0; k < 32; ++k) {
            float a = r[k];
            a0 += a * p.W5a[k*16 + f0];
            a1 += a * p.W5a[k*16 + f0 + 1];
        }
        sBase[n*18 + f0]     = a0;
        sBase[n*18 + f0 + 1] = a1;
    }
    __syncthreads();
    if (tid < 64) {
        const int n = tid >> 1, col = tid & 1;
        float acc = p.b5b[col];
        const float* r = sBase + n*18;
        #pragma unroll
        for (int k = 0; k < 16; ++k) acc += r[k] * p.W5b[k*2 + col];
        if (col == 0) p.out[b*32 + n] = acc;
        else          p.out[32768 + b*32 + n] = 1.0f / acc;
    }
}

extern "C" void kernel_launch(void* const* d_in, const int* in_sizes, int n_in,
                              void* d_out, int out_size) {
    const int has_iter = (n_in >= 32) ? 1 : 0;
    const int base = has_iter ? 8 : 7;

    GnnParams p;
    p.node0 = (const float*)d_in[0];
    p.edge  = (const float*)d_in[1];
    p.h0    = (const float*)d_in[2];
    p.mean  = (const float*)d_in[3];
    p.vari  = (const float*)d_in[4];
    p.iterp = has_iter ? (const int*)d_in[7] : nullptr;
    p.W1a = (const float*)d_in[base+0];  p.b1a = (const float*)d_in[base+1];
    p.W2a = (const float*)d_in[base+2];  p.b2a = (const float*)d_in[base+3];
    p.W2b = (const float*)d_in[base+4];  p.b2b = (const float*)d_in[base+5];
    p.W2c = (const float*)d_in[base+6];  p.b2c = (const float*)d_in[base+7];
    p.Wih = (const float*)d_in[base+8];  p.Whh = (const float*)d_in[base+9];
    p.bih = (const float*)d_in[base+10]; p.bhh = (const float*)d_in[base+11];
    p.W3b = (const float*)d_in[base+12]; p.b3b = (const float*)d_in[base+13];
    p.W4a = (const float*)d_in[base+14]; p.b4a = (const float*)d_in[base+15];
    p.W4b = (const float*)d_in[base+16]; p.b4b = (const float*)d_in[base+17];
    p.W4c = (const float*)d_in[base+18]; p.b4c = (const float*)d_in[base+19];
    p.W5a = (const float*)d_in[base+20]; p.b5a = (const float*)d_in[base+21];
    p.W5b = (const float*)d_in[base+22]; p.b5b = (const float*)d_in[base+23];
    p.out = (float*)d_out;

    cudaFuncSetAttribute(gnn_kernel,
                         cudaFuncAttributeMaxDynamicSharedMemorySize,
                         SMEM_FLOATS * (int)sizeof(float));
    gnn_kernel<<<1024, NT, SMEM_FLOATS * sizeof(float)>>>(p);
}

// round 12
// speedup vs baseline: 2.0282x; 1.0280x over previous
#include <cuda_runtime.h>
#include <math.h>

#define NT 256
typedef unsigned long long ull;

// Shared layout (float offsets)
#define OFF_NT    0        // nodeT [32 feat][32 node] stride 33 = 1056
#define OFF_H     1056     // [32][65] = 2080
#define OFF_MI    3136     // [32][36] = 1152
#define OFF_EDGE  4288     // [992][2] = 1984
#define OFF_BASE  6272     // [32][68] = 2176 (stride 68 -> 16B aligned rows)
#define OFF_PROJ  8448     // [32][68] = 2176
#define OFF_A     10624    // staging W2a[0:64]+b2a (4160) / readout t1 (2176)
#define OFF_W2B2  14784    // W2b: 2048 floats
#define OFF_W2C2  16832    // wCt paired-transposed W2c: 512 ull = 1024 floats
#define OFF_W45S  17856    // w45 interleaved: 128 floats (ull[2t]=row64 pair t, [2t+1]=row65 pair t)
#define OFF_B2B   17984    // 32
#define OFF_B2C   18016    // 32
#define SMEM_FLOATS 18048  // 72,192 B -> 2 CTAs/SM

__device__ __forceinline__ float rcp_fast(float x) {
    float r; asm("rcp.approx.f32 %0, %1;" : "=f"(r) : "f"(x)); return r;
}
__device__ __forceinline__ float ex2_fast(float x) {
    float r; asm("ex2.approx.f32 %0, %1;" : "=f"(r) : "f"(x)); return r;
}
__device__ __forceinline__ ull pack2(float lo, float hi) {
    ull r; asm("mov.b64 %0, {%1, %2};" : "=l"(r) : "f"(lo), "f"(hi)); return r;
}
__device__ __forceinline__ ull dup2(float x) { return pack2(x, x); }
__device__ __forceinline__ void unpack2(ull v, float& lo, float& hi) {
    asm("mov.b64 {%0, %1}, %2;" : "=f"(lo), "=f"(hi) : "l"(v));
}
__device__ __forceinline__ ull fma2(ull a, ull b, ull c) {
    ull d; asm("fma.rn.f32x2 %0, %1, %2, %3;" : "=l"(d) : "l"(a), "l"(b), "l"(c));
    return d;
}
__device__ __forceinline__ ull add2(ull a, ull b) {
    ull d; asm("add.rn.f32x2 %0, %1, %2;" : "=l"(d) : "l"(a), "l"(b));
    return d;
}
__device__ __forceinline__ ull mul2(ull a, ull b) {
    ull d; asm("mul.rn.f32x2 %0, %1, %2;" : "=l"(d) : "l"(a), "l"(b));
    return d;
}

// Packed GELU on an f32x2 pair: A&S 7.1.26 erf; poly on FMA pipe, 2 RCP + 2 EX2 on MUFU.
__device__ __forceinline__ ull gelu2(ull x2) {
    ull s2 = mul2(x2, dup2(0.7071067811865476f));
    ull a2 = s2 & 0x7FFFFFFF7FFFFFFFULL;
    ull v2 = fma2(a2, dup2(0.3275911f), dup2(1.0f));
    float v0, v1; unpack2(v2, v0, v1);
    ull r2 = pack2(rcp_fast(v0), rcp_fast(v1));
    ull u2 = mul2(a2, a2);
    ull y2 = mul2(u2, dup2(-1.4426950408889634f));
    float y0, y1; unpack2(y2, y0, y1);
    ull e2 = pack2(ex2_fast(y0), ex2_fast(y1));
    ull q2 = dup2(1.061405429f);
    q2 = fma2(q2, r2, dup2(-1.453152027f));
    q2 = fma2(q2, r2, dup2(1.421413741f));
    q2 = fma2(q2, r2, dup2(-0.284496736f));
    q2 = fma2(q2, r2, dup2(0.254829592f));
    q2 = mul2(q2, r2);
    ull t2 = mul2(q2, e2);
    ull E2 = fma2(t2, dup2(-1.0f), dup2(1.0f));   // erf(|s|) >= 0
    E2 = E2 | (s2 & 0x8000000080000000ULL);       // copysign
    ull hx = mul2(x2, dup2(0.5f));
    return fma2(hx, E2, hx);                      // 0.5x(1+E)
}
// Scalar GELU (GRU etc.)
__device__ __forceinline__ float gelu_f(float x) {
    float s = x * 0.7071067811865476f;
    float a = fabsf(s);
    float v = fmaf(0.3275911f, a, 1.0f);
    float r = rcp_fast(v);
    float ex = ex2_fast(-a * a * 1.4426950408889634f);
    float q = 1.061405429f;
    q = fmaf(q, r, -1.453152027f);
    q = fmaf(q, r, 1.421413741f);
    q = fmaf(q, r, -0.284496736f);
    q = fmaf(q, r, 0.254829592f);
    q = q * r;
    float E = fmaf(-q, ex, 1.0f);
    E = copysignf(E, s);
    return 0.5f * x * (1.0f + E);
}
__device__ __forceinline__ float sigm_f(float x) {
    return rcp_fast(1.0f + ex2_fast(-x * 1.4426950408889634f));
}

struct GnnParams {
    const float *node0, *edge, *h0, *mean, *vari;
    const int   *iterp;
    const float *W1a, *b1a, *W2a, *b2a, *W2b, *b2b, *W2c, *b2c;
    const float *Wih, *Whh, *bih, *bhh, *W3b, *b3b;
    const float *W4a, *b4a, *W4b, *b4b, *W4c, *b4c, *W5a, *b5a, *W5b, *b5b;
    float *out;
};

__global__ __launch_bounds__(NT, 2)
void gnn_kernel(GnnParams p) {
    extern __shared__ float sm[];
    const int tid  = threadIdx.x;
    const int b    = blockIdx.x;
    const int warp = tid >> 5, lane = tid & 31;

    float* sNT   = sm + OFF_NT;
    float* sH    = sm + OFF_H;     // stride 65
    float* sMi   = sm + OFF_MI;    // stride 36
    float* sEdge = sm + OFF_EDGE;
    float* sBase = sm + OFF_BASE;  // stride 68
    float* sProj = sm + OFF_PROJ;  // stride 68
    float* bufA  = sm + OFF_A;
    const ull*   wB   = (const ull*)(sm + OFF_W2B2);
    const ull*   wCt  = (const ull*)(sm + OFF_W2C2);
    const float* w45x = sm + OFF_W45S;
    const ull*   bB   = (const ull*)(sm + OFF_B2B);
    const float* bCs  = sm + OFF_B2C;

    // ---- init copies (once) ----
    for (int i = tid; i < 992*2; i += NT) sEdge[i] = p.edge[b*1984 + i];
    for (int i = tid; i < 32*64; i += NT) {
        int n = i >> 6, k = i & 63;
        sH[n*65 + k] = p.h0[b*2048 + i];
    }
    for (int i = tid; i < 2048;  i += NT) sm[OFF_W2B2 + i] = p.W2b[i];
    for (int i = tid; i < 512;   i += NT) {       // wCt[c*16+qp] = (W2c[2qp][c], W2c[2qp+1][c])
        int c = i >> 4, qp = i & 15;
        ((ull*)(sm + OFF_W2C2))[i] =
            pack2(p.W2c[(2*qp)*32 + c], p.W2c[(2*qp+1)*32 + c]);
    }
    for (int i = tid; i < 128;   i += NT) {       // interleave w45: [4t+0,1]=row64 pair t; [4t+2,3]=row65 pair t
        int t = i >> 2, sub = i & 3;
        int src = (sub < 2) ? (64*64 + 2*t + sub) : (64*64 + 64 + 2*t + (sub - 2));
        sm[OFF_W45S + i] = p.W2a[src];
    }
    for (int i = tid; i < 32;    i += NT) {
        sm[OFF_B2B + i] = p.b2b[i];
        sm[OFF_B2C + i] = p.b2c[i];
    }
    if (tid < 32) {
        sMi[tid*36 + 32] = p.mean[b*32 + tid];
        sMi[tid*36 + 33] = 1.0f / p.vari[b*32 + tid];
    }
    for (int i = tid; i < 1024; i += NT) sBase[i] = p.node0[b*1024 + i];
    for (int i = tid; i < 4096; i += NT) bufA[i] = p.W2a[i];
    for (int i = tid + 4096; i < 4160; i += NT) bufA[i] = p.b2a[i - 4096];
    __syncthreads();

    // ---- node = node0 @ W1a + b1a (write transposed into sNT) ----
    {
        const int n = tid >> 3, f0 = (tid & 7) << 2;
        float a0 = p.b1a[f0], a1 = p.b1a[f0+1], a2 = p.b1a[f0+2], a3 = p.b1a[f0+3];
        const float* r = sBase + n*32;
        #pragma unroll 8
        for (int k = 0; k < 32; ++k) {
            float a = r[k];
            float4 w = *(const float4*)(p.W1a + k*32 + f0);
            a0 += a*w.x; a1 += a*w.y; a2 += a*w.z; a3 += a*w.w;
        }
        sNT[(f0+0)*33 + n] = a0; sNT[(f0+1)*33 + n] = a1;
        sNT[(f0+2)*33 + n] = a2; sNT[(f0+3)*33 + n] = a3;
    }
    __syncthreads();

    const int iters = p.iterp ? *p.iterp : 3;

    for (int it = 0; it < iters; ++it) {
        // ---- base = node@W2a[0:32]+b2a ; proj = node@W2a[32:64] ----
        {
            const int n = tid >> 3, c0 = (tid & 7) << 3;
            ull bacc[4], pacc[4];
            {
                ulonglong2 b0 = *(const ulonglong2*)(bufA + 4096 + c0);
                ulonglong2 b1 = *(const ulonglong2*)(bufA + 4096 + c0 + 4);
                bacc[0]=b0.x; bacc[1]=b0.y; bacc[2]=b1.x; bacc[3]=b1.y;
            }
            const ull z = dup2(0.0f);
            #pragma unroll
            for (int o = 0; o < 4; ++o) pacc[o] = z;
            #pragma unroll 4
            for (int k = 0; k < 32; ++k) {
                ull aa = dup2(sNT[k*33 + n]);
                ulonglong2 wb0 = *(const ulonglong2*)(bufA + k*64 + c0);
                ulonglong2 wb1 = *(const ulonglong2*)(bufA + k*64 + c0 + 4);
                ulonglong2 wp0 = *(const ulonglong2*)(bufA + (32+k)*64 + c0);
                ulonglong2 wp1 = *(const ulonglong2*)(bufA + (32+k)*64 + c0 + 4);
                bacc[0] = fma2(aa, wb0.x, bacc[0]); bacc[1] = fma2(aa, wb0.y, bacc[1]);
                bacc[2] = fma2(aa, wb1.x, bacc[2]); bacc[3] = fma2(aa, wb1.y, bacc[3]);
                pacc[0] = fma2(aa, wp0.x, pacc[0]); pacc[1] = fma2(aa, wp0.y, pacc[1]);
                pacc[2] = fma2(aa, wp1.x, pacc[2]); pacc[3] = fma2(aa, wp1.y, pacc[3]);
            }
            *(ulonglong2*)(sBase + n*68 + c0)     = make_ulonglong2(bacc[0], bacc[1]);
            *(ulonglong2*)(sBase + n*68 + c0 + 4) = make_ulonglong2(bacc[2], bacc[3]);
            *(ulonglong2*)(sProj + n*68 + c0)     = make_ulonglong2(pacc[0], pacc[1]);
            *(ulonglong2*)(sProj + n*68 + c0 + 4) = make_ulonglong2(pacc[2], pacc[3]);
        }
        __syncthreads();

        // ---- edge phase: warp = node i, lane = edge q; register-resident ----
        for (int pass = 0; pass < 4; ++pass) {
            const int i = pass * 8 + warp;
            const int q = (lane < 31) ? lane : 30;
            const int j = q + (q >= i);
            const ull ev = *(const ull*)(sEdge + (i*31 + q)*2);
            float e0f, e1f; unpack2(ev, e0f, e1f);
            const ull e0d = dup2(e0f), e1d = dup2(e1f);
            const float* prj = sProj + j*68;
            const float* bas = sBase + i*68;

            ull acc[16];
            #pragma unroll
            for (int cp = 0; cp < 16; ++cp) acc[cp] = bB[cp];

            #pragma unroll 4
            for (int tp = 0; tp < 16; ++tp) {     // two col-pairs (k-pairs) per iter
                ulonglong2 bp = *(const ulonglong2*)(bas + 4*tp);
                ulonglong2 pp = *(const ulonglong2*)(prj + 4*tp);
                ulonglong2 wa = *(const ulonglong2*)(w45x + 8*tp);
                ulonglong2 wbv = *(const ulonglong2*)(w45x + 8*tp + 4);
                ull u0 = add2(bp.x, pp.x);
                u0 = fma2(e0d, wa.x, u0); u0 = fma2(e1d, wa.y, u0);
                ull u1 = add2(bp.y, pp.y);
                u1 = fma2(e0d, wbv.x, u1); u1 = fma2(e1d, wbv.y, u1);
                ull g0p = gelu2(u0), g1p = gelu2(u1);
                float ga, gb, gc, gd;
                unpack2(g0p, ga, gb); unpack2(g1p, gc, gd);
                ull A0 = dup2(ga), A1 = dup2(gb), A2 = dup2(gc), A3 = dup2(gd);
                const int k0 = 4*tp;
                #pragma unroll
                for (int cp2 = 0; cp2 < 8; ++cp2) {
                    ulonglong2 w0 = *(const ulonglong2*)(wB + (k0+0)*16 + 2*cp2);
                    ulonglong2 w1 = *(const ulonglong2*)(wB + (k0+1)*16 + 2*cp2);
                    ulonglong2 w2 = *(const ulonglong2*)(wB + (k0+2)*16 + 2*cp2);
                    ulonglong2 w3 = *(const ulonglong2*)(wB + (k0+3)*16 + 2*cp2);
                    acc[2*cp2]   = fma2(A0, w0.x, acc[2*cp2]);
                    acc[2*cp2+1] = fma2(A0, w0.y, acc[2*cp2+1]);
                    acc[2*cp2]   = fma2(A1, w1.x, acc[2*cp2]);
                    acc[2*cp2+1] = fma2(A1, w1.y, acc[2*cp2+1]);
                    acc[2*cp2]   = fma2(A2, w2.x, acc[2*cp2]);
                    acc[2*cp2+1] = fma2(A2, w2.y, acc[2*cp2+1]);
                    acc[2*cp2]   = fma2(A3, w3.x, acc[2*cp2]);
                    acc[2*cp2+1] = fma2(A3, w3.y, acc[2*cp2+1]);
                }
            }

            // gelu m2 in place (packed): acc[cp] = (m2_{2cp}, m2_{2cp+1})
            #pragma unroll
            for (int cp = 0; cp < 16; ++cp) acc[cp] = gelu2(acc[cp]);

            // layer 3: col-PAIR at a time, paired-k fma2 + horizontal add
            const ull mask2 = dup2((lane < 31) ? 1.0f : 0.0f);
            float m3[32];
            #pragma unroll
            for (int c2 = 0; c2 < 16; ++c2) {
                float b0, b1;
                {
                    ull bc = *(const ull*)(bCs + 2*c2);
                    unpack2(bc, b0, b1);
                }
                ull s0a = pack2(b0, 0.0f), s0b = dup2(0.0f);
                ull s1a = pack2(b1, 0.0f), s1b = dup2(0.0f);
                const ull* wr0 = wCt + (2*c2)*16;
                const ull* wr1 = wCt + (2*c2+1)*16;
                #pragma unroll
                for (int jj = 0; jj < 8; ++jj) {
                    ulonglong2 w0 = *(const ulonglong2*)(wr0 + 2*jj);
                    ulonglong2 w1 = *(const ulonglong2*)(wr1 + 2*jj);
                    s0a = fma2(acc[2*jj],   w0.x, s0a);
                    s0b = fma2(acc[2*jj+1], w0.y, s0b);
                    s1a = fma2(acc[2*jj],   w1.x, s1a);
                    s1b = fma2(acc[2*jj+1], w1.y, s1b);
                }
                s0a = add2(s0a, s0b);
                s1a = add2(s1a, s1b);
                float l0, h0, l1, h1;
                unpack2(s0a, l0, h0); unpack2(s1a, l1, h1);
                ull g = gelu2(pack2(l0 + h0, l1 + h1));
                g = mul2(g, mask2);
                unpack2(g, m3[2*c2], m3[2*c2+1]);
            }

            // scalar butterfly transpose-reduce over 32 cols (31 shfl)
            #pragma unroll
            for (int s = 0; s < 5; ++s) {
                const int off = 1 << s;
                const int h = 16 >> s;
                const bool keep_low = ((lane >> s) & 1) == 0;
                #pragma unroll
                for (int r = 0; r < 16; ++r) {
                    if (r < h) {
                        float send = keep_low ? m3[r + h] : m3[r];
                        float recv = __shfl_xor_sync(0xffffffffu, send, off);
                        float mine = keep_low ? m3[r] : m3[r + h];
                        m3[r] = mine + recv;
                    }
                }
            }
            {
                const int e = ((lane & 1) << 4) | (((lane >> 1) & 1) << 3) |
                              (((lane >> 2) & 1) << 2) | (((lane >> 3) & 1) << 1) |
                              ((lane >> 4) & 1);
                sMi[i*36 + e] = m3[0];
            }
        }
        __syncthreads();

        // ---- GRU cell (GELU new gate), packed col-pairs ----
        {
            const int n  = tid >> 3;
            const int c0 = (tid & 7) << 3;
            ull ar[4], az[4], an_[4], hn_[4];
            #pragma unroll
            for (int o = 0; o < 4; ++o) {
                ull bi_r = *(const ull*)(p.bih + c0 + 2*o);
                ull bh_r = *(const ull*)(p.bhh + c0 + 2*o);
                ull bi_z = *(const ull*)(p.bih + 64 + c0 + 2*o);
                ull bh_z = *(const ull*)(p.bhh + 64 + c0 + 2*o);
                ar[o]  = add2(bi_r, bh_r);
                az[o]  = add2(bi_z, bh_z);
                an_[o] = *(const ull*)(p.bih + 128 + c0 + 2*o);
                hn_[o] = *(const ull*)(p.bhh + 128 + c0 + 2*o);
            }
            const float* mi = sMi + n*36;
            #pragma unroll 2
            for (int k = 0; k < 34; ++k) {
                ull aa = dup2(mi[k]);
                const float* w = p.Wih + k*192;
                ulonglong2 r01 = *(const ulonglong2*)(w + c0);
                ulonglong2 r23 = *(const ulonglong2*)(w + c0 + 4);
                ulonglong2 z01 = *(const ulonglong2*)(w + 64 + c0);
                ulonglong2 z23 = *(const ulonglong2*)(w + 64 + c0 + 4);
                ulonglong2 n01 = *(const ulonglong2*)(w + 128 + c0);
                ulonglong2 n23 = *(const ulonglong2*)(w + 128 + c0 + 4);
                ar[0]=fma2(aa,r01.x,ar[0]); ar[1]=fma2(aa,r01.y,ar[1]);
                ar[2]=fma2(aa,r23.x,ar[2]); ar[3]=fma2(aa,r23.y,ar[3]);
                az[0]=fma2(aa,z01.x,az[0]); az[1]=fma2(aa,z01.y,az[1]);
                az[2]=fma2(aa,z23.x,az[2]); az[3]=fma2(aa,z23.y,az[3]);
                an_[0]=fma2(aa,n01.x,an_[0]); an_[1]=fma2(aa,n01.y,an_[1]);
                an_[2]=fma2(aa,n23.x,an_[2]); an_[3]=fma2(aa,n23.y,an_[3]);
            }
            const float* hv = sH + n*65;
            #pragma unroll 2
            for (int k = 0; k < 64; ++k) {
                ull aa = dup2(hv[k]);
                const float* w = p.Whh + k*192;
                ulonglong2 r01 = *(const ulonglong2*)(w + c0);
                ulonglong2 r23 = *(const ulonglong2*)(w + c0 + 4);
                ulonglong2 z01 = *(const ulonglong2*)(w + 64 + c0);
                ulonglong2 z23 = *(const ulonglong2*)(w + 64 + c0 + 4);
                ulonglong2 n01 = *(const ulonglong2*)(w + 128 + c0);
                ulonglong2 n23 = *(const ulonglong2*)(w + 128 + c0 + 4);
                ar[0]=fma2(aa,r01.x,ar[0]); ar[1]=fma2(aa,r01.y,ar[1]);
                ar[2]=fma2(aa,r23.x,ar[2]); ar[3]=fma2(aa,r23.y,ar[3]);
                az[0]=fma2(aa,z01.x,az[0]); az[1]=fma2(aa,z01.y,az[1]);
                az[2]=fma2(aa,z23.x,az[2]); az[3]=fma2(aa,z23.y,az[3]);
                hn_[0]=fma2(aa,n01.x,hn_[0]); hn_[1]=fma2(aa,n01.y,hn_[1]);
                hn_[2]=fma2(aa,n23.x,hn_[2]); hn_[3]=fma2(aa,n23.y,hn_[3]);
            }
            float hnew[8];
            #pragma unroll
            for (int o = 0; o < 4; ++o) {
                float r0, r1, z0, z1, in0, in1, hn0, hn1;
                unpack2(ar[o], r0, r1);
                unpack2(az[o], z0, z1);
                unpack2(an_[o], in0, in1);
                unpack2(hn_[o], hn0, hn1);
                float rr0 = sigm_f(r0), rr1 = sigm_f(r1);
                float zz0 = sigm_f(z0), zz1 = sigm_f(z1);
                float g0, g1;
                unpack2(gelu2(pack2(fmaf(rr0, hn0, in0), fmaf(rr1, hn1, in1))), g0, g1);
                hnew[2*o]   = (1.0f - zz0) * g0 + zz0 * hv[c0 + 2*o];
                hnew[2*o+1] = (1.0f - zz1) * g1 + zz1 * hv[c0 + 2*o + 1];
            }
            __syncthreads();
            #pragma unroll
            for (int o = 0; o < 8; ++o) sH[n*65 + c0 + o] = hnew[o];
        }
        __syncthreads();

        // ---- node = h @ W3b + b3b  (packed, write transposed into sNT) ----
        {
            const int n = tid >> 3, f0 = (tid & 7) << 2;
            ull a01 = *(const ull*)(p.b3b + f0);
            ull a23 = *(const ull*)(p.b3b + f0 + 2);
            const float* hv = sH + n*65;
            #pragma unroll 4
            for (int k = 0; k < 64; ++k) {
                ull aa = dup2(hv[k]);
                ulonglong2 w2 = *(const ulonglong2*)(p.W3b + k*32 + f0);
                a01 = fma2(aa, w2.x, a01);
                a23 = fma2(aa, w2.y, a23);
            }
            float v0, v1, v2, v3;
            unpack2(a01, v0, v1); unpack2(a23, v2, v3);
            sNT[(f0+0)*33 + n] = v0; sNT[(f0+1)*33 + n] = v1;
            sNT[(f0+2)*33 + n] = v2; sNT[(f0+3)*33 + n] = v3;
        }
        __syncthreads();
    }

    // ---- readout (scratch: bufA=t1, sBase=t2, sProj=t3, sBase=t4) ----
    {   // t1 = node @ W4a + b4a : [32][68]
        const int n = tid >> 3, f0 = (tid & 7) << 3;
        ull acc[4];
        acc[0] = *(const ull*)(p.b4a + f0);
        acc[1] = *(const ull*)(p.b4a + f0 + 2);
        acc[2] = *(const ull*)(p.b4a + f0 + 4);
        acc[3] = *(const ull*)(p.b4a + f0 + 6);
        #pragma unroll 4
        for (int k = 0; k < 32; ++k) {
            ull aa = dup2(sNT[k*33 + n]);
            ulonglong2 w0 = *(const ulonglong2*)(p.W4a + k*64 + f0);
            ulonglong2 w1 = *(const ulonglong2*)(p.W4a + k*64 + f0 + 4);
            acc[0] = fma2(aa, w0.x, acc[0]); acc[1] = fma2(aa, w0.y, acc[1]);
            acc[2] = fma2(aa, w1.x, acc[2]); acc[3] = fma2(aa, w1.y, acc[3]);
        }
        *(ulonglong2*)(bufA + n*68 + f0)     = make_ulonglong2(acc[0], acc[1]);
        *(ulonglong2*)(bufA + n*68 + f0 + 4) = make_ulonglong2(acc[2], acc[3]);
    }
    __syncthreads();
    {   // t2 = t1 @ W4b + b4b : [32][36] into sBase
        const int n = tid >> 3, f0 = (tid & 7) << 2;
        ull a01 = *(const ull*)(p.b4b + f0);
        ull a23 = *(const ull*)(p.b4b + f0 + 2);
        const float* r = bufA + n*68;
        #pragma unroll 4
        for (int k = 0; k < 64; ++k) {
            ull aa = dup2(r[k]);
            ulonglong2 w2 = *(const ulonglong2*)(p.W4b + k*32 + f0);
            a01 = fma2(aa, w2.x, a01);
            a23 = fma2(aa, w2.y, a23);
        }
        *(ull*)(sBase + n*36 + f0)     = a01;
        *(ull*)(sBase + n*36 + f0 + 2) = a23;
    }
    __syncthreads();
    {   // t3 = t2 @ W4c + b4c : [32][36] into sProj
        const int n = tid >> 3, f0 = (tid & 7) << 2;
        ull a01 = *(const ull*)(p.b4c + f0);
        ull a23 = *(const ull*)(p.b4c + f0 + 2);
        const float* r = sBase + n*36;
        #pragma unroll 4
        for (int k = 0; k < 32; ++k) {
            ull aa = dup2(r[k]);
            ulonglong2 w2 = *(const ulonglong2*)(p.W4c + k*32 + f0);
            a01 = fma2(aa, w2.x, a01);
            a23 = fma2(aa, w2.y, a23);
        }
        *(ull*)(sProj + n*36 + f0)     = a01;
        *(ull*)(sProj + n*36 + f0 + 2) = a23;
    }
    __syncthreads();
    {   // t4 = t3 @ W5a + b5a : [32][18] into sBase
        const int n = tid >> 3, f0 = (tid & 7) << 1;
        float a0 = p.b5a[f0], a1 = p.b5a[f0 + 1];
        const float* r = sProj + n*36;
        #pragma unroll 8
        for (int k = 0; k < 32; ++k) {
            float a = r[k];
            a0 += a * p.W5a[k*16 + f0];
            a1 += a * p.W5a[k*16 + f0 + 1];
        }
        sBase[n*18 + f0]     = a0;
        sBase[n*18 + f0 + 1] = a1;
    }
    __syncthreads();
    if (tid < 64) {
        const int n = tid >> 1, col = tid & 1;
        float acc = p.b5b[col];
        const float* r = sBase + n*18;
        #pragma unroll
        for (int k = 0; k < 16; ++k) acc += r[k] * p.W5b[k*2 + col];
        if (col == 0) p.out[b*32 + n] = acc;
        else          p.out[32768 + b*32 + n] = 1.0f / acc;
    }
}

extern "C" void kernel_launch(void* const* d_in, const int* in_sizes, int n_in,
                              void* d_out, int out_size) {
    const int has_iter = (n_in >= 32) ? 1 : 0;
    const int base = has_iter ? 8 : 7;

    GnnParams p;
    p.node0 = (const float*)d_in[0];
    p.edge  = (const float*)d_in[1];
    p.h0    = (const float*)d_in[2];
    p.mean  = (const float*)d_in[3];
    p.vari  = (const float*)d_in[4];
    p.iterp = has_iter ? (const int*)d_in[7] : nullptr;
    p.W1a = (const float*)d_in[base+0];  p.b1a = (const float*)d_in[base+1];
    p.W2a = (const float*)d_in[base+2];  p.b2a = (const float*)d_in[base+3];
    p.W2b = (const float*)d_in[base+4];  p.b2b = (const float*)d_in[base+5];
    p.W2c = (const float*)d_in[base+6];  p.b2c = (const float*)d_in[base+7];
    p.Wih = (const float*)d_in[base+8];  p.Whh = (const float*)d_in[base+9];
    p.bih = (const float*)d_in[base+10]; p.bhh = (const float*)d_in[base+11];
    p.W3b = (const float*)d_in[base+12]; p.b3b = (const float*)d_in[base+13];
    p.W4a = (const float*)d_in[base+14]; p.b4a = (const float*)d_in[base+15];
    p.W4b = (const float*)d_in[base+16]; p.b4b = (const float*)d_in[base+17];
    p.W4c = (const float*)d_in[base+18]; p.b4c = (const float*)d_in[base+19];
    p.W5a = (const float*)d_in[base+20]; p.b5a = (const float*)d_in[base+21];
    p.W5b = (const float*)d_in[base+22]; p.b5b = (const float*)d_in[base+23];
    p.out = (float*)d_out;

    cudaFuncSetAttribute(gnn_kernel,
                         cudaFuncAttributeMaxDynamicSharedMemorySize,
                         SMEM_FLOATS * (int)sizeof(float));
    gnn_kernel<<<1024, NT, SMEM_FLOATS * sizeof(float)>>>(p);
}